// round 14
// baseline (speedup 1.0000x reference)
#include <cuda_runtime.h>
#include <cuda_bf16.h>
#include <math_constants.h>
#include <cstdint>

#define Bq  4
#define Tt  2048
#define Dd  2048
#define Hh  16
#define DHd 128
#define Mm  (Bq * Tt)        // 8192
#define SCALE 0.08838834764831845f  // DH^-0.5

// ---------------------------------------------------------------------------
// Persistent bf16 hi/lo tensors (allocation-free rule: __device__ globals)
// ---------------------------------------------------------------------------
__device__ __align__(256) __nv_bfloat16 g_xh[Mm * Dd];
__device__ __align__(256) __nv_bfloat16 g_xl[Mm * Dd];
__device__ __align__(256) __nv_bfloat16 g_wth[4][Dd * Dd];   // W^T hi, [N][K]
__device__ __align__(256) __nv_bfloat16 g_wtl[4][Dd * Dd];   // W^T lo
__device__ __align__(256) __nv_bfloat16 g_qh[Bq * Hh * Tt * DHd];
__device__ __align__(256) __nv_bfloat16 g_ql[Bq * Hh * Tt * DHd];
__device__ __align__(256) __nv_bfloat16 g_kh[Bq * Hh * Tt * DHd];
__device__ __align__(256) __nv_bfloat16 g_kl[Bq * Hh * Tt * DHd];
__device__ __align__(256) __nv_bfloat16 g_vth[Bq * Hh * DHd * Tt];  // [b,h,d,t]
__device__ __align__(256) __nv_bfloat16 g_vtl[Bq * Hh * DHd * Tt];
__device__ __align__(256) __nv_bfloat16 g_atth[Bq * Tt * Dd];
__device__ __align__(256) __nv_bfloat16 g_attl[Bq * Tt * Dd];

// ===========================================================================
// Helpers
// ===========================================================================
__device__ __forceinline__ uint32_t smem_u32(const void* p) {
    uint32_t a;
    asm("{ .reg .u64 t; cvta.to.shared.u64 t, %1; cvt.u32.u64 %0, t; }" : "=r"(a) : "l"(p));
    return a;
}
__device__ __forceinline__ void cp16(uint32_t dst, const void* src) {
    asm volatile("cp.async.cg.shared.global [%0], [%1], 16;" :: "r"(dst), "l"(src));
}
#define CP_COMMIT() asm volatile("cp.async.commit_group;" ::: "memory")
#define CP_WAIT0()  asm volatile("cp.async.wait_group 0;" ::: "memory")
#define CP_WAIT1()  asm volatile("cp.async.wait_group 1;" ::: "memory")

__device__ __forceinline__ void mma_bf16(float* c, const uint32_t* a,
                                         uint32_t b0, uint32_t b1) {
    asm volatile(
        "mma.sync.aligned.m16n8k16.row.col.f32.bf16.bf16.f32 "
        "{%0,%1,%2,%3}, {%4,%5,%6,%7}, {%8,%9}, {%0,%1,%2,%3};"
        : "+f"(c[0]), "+f"(c[1]), "+f"(c[2]), "+f"(c[3])
        : "r"(a[0]), "r"(a[1]), "r"(a[2]), "r"(a[3]), "r"(b0), "r"(b1));
}
__device__ __forceinline__ void ldsm_x4(uint32_t* r, uint32_t addr) {
    asm volatile("ldmatrix.sync.aligned.m8n8.x4.shared.b16 {%0,%1,%2,%3}, [%4];"
        : "=r"(r[0]), "=r"(r[1]), "=r"(r[2]), "=r"(r[3]) : "r"(addr));
}
__device__ __forceinline__ uint32_t pack_bf16(float v0, float v1) {
    uint32_t h;
    asm("cvt.rn.bf16x2.f32 %0, %1, %2;" : "=r"(h) : "f"(v1), "f"(v0));
    return h;
}
// Split pair of fp32 into bf16x2 hi + bf16x2 residual (lower 16 bits = v0)
__device__ __forceinline__ void bf16_split2(float v0, float v1,
                                            uint32_t& hi, uint32_t& lo) {
    uint32_t h = pack_bf16(v0, v1);
    float f0 = __uint_as_float(h << 16);
    float f1 = __uint_as_float(h & 0xffff0000u);
    lo = pack_bf16(v0 - f0, v1 - f1);
    hi = h;
}

// ===========================================================================
// Conversion kernels
// ===========================================================================
__global__ __launch_bounds__(256)
void conv_x_kernel(const float* __restrict__ src,
                   __nv_bfloat16* __restrict__ hi, __nv_bfloat16* __restrict__ lo)
{
    const size_t i4 = ((size_t)blockIdx.x * 256 + threadIdx.x) * 4;
    float4 v = *(const float4*)(src + i4);
    uint32_t h0, l0, h1, l1;
    bf16_split2(v.x, v.y, h0, l0);
    bf16_split2(v.z, v.w, h1, l1);
    *(uint2*)(hi + i4) = make_uint2(h0, h1);
    *(uint2*)(lo + i4) = make_uint2(l0, l1);
}

// Transpose all 4 W [K][N] -> W^T [N][K], split to bf16 hi/lo. gridDim.z = 4.
__global__ __launch_bounds__(256)
void conv_w_all(const float* __restrict__ W0, const float* __restrict__ W1,
                const float* __restrict__ W2, const float* __restrict__ W3,
                __nv_bfloat16* __restrict__ Th, __nv_bfloat16* __restrict__ Tl)
{
    const int z = blockIdx.z;
    const float* W = (z == 0) ? W0 : (z == 1) ? W1 : (z == 2) ? W2 : W3;
    __nv_bfloat16* th = Th + (size_t)z * Dd * Dd;
    __nv_bfloat16* tl = Tl + (size_t)z * Dd * Dd;

    __shared__ float tile[32][33];
    int x = blockIdx.x * 32 + threadIdx.x;
    int y = blockIdx.y * 32 + threadIdx.y;
#pragma unroll
    for (int j = 0; j < 32; j += 8)
        tile[threadIdx.y + j][threadIdx.x] = W[(size_t)(y + j) * Dd + x];
    __syncthreads();
    int n = blockIdx.x * 32 + threadIdx.y;
    int k = blockIdx.y * 32 + threadIdx.x;
#pragma unroll
    for (int j = 0; j < 32; j += 8) {
        float v = tile[threadIdx.x][threadIdx.y + j];
        __nv_bfloat16 h = __float2bfloat16(v);
        __nv_bfloat16 l = __float2bfloat16(v - __bfloat162float(h));
        th[(size_t)(n + j) * Dd + k] = h;
        tl[(size_t)(n + j) * Dd + k] = l;
    }
}

// ===========================================================================
// bf16 hi/lo tensor-core GEMM core (R11 config: best measured).
// BM=BN=128, BK=32, 256 threads (8 warps 2x4), warp tile 64x32.
// 3-stage cp.async ring (96KB) at 2 CTAs/SM. Dense 64B rows + XOR swizzle.
// ===========================================================================
#define GBM 128
#define GBN 128
#define GBK 32
#define TILEB 8192                    // 128 rows * 64B
#define STAGEB (4 * TILEB)            // 32768: Ah|Al|Bh|Bl
#define GEMM_SMEM (3 * STAGEB)        // 98304 -> 2 CTAs/SM

__device__ __forceinline__ void load_stage(uint32_t sdst,
        const __nv_bfloat16* __restrict__ Ah, const __nv_bfloat16* __restrict__ Al,
        const __nv_bfloat16* __restrict__ Bh, const __nv_bfloat16* __restrict__ Bl,
        int m0, int n0, int k0)
{
    const int tid = threadIdx.x;
#pragma unroll
    for (int l = 0; l < 2; l++) {
        int e = tid + 256 * l;
        int r = e >> 2, c = e & 3;
        int cp_ = c ^ ((r >> 1) & 3);
        uint32_t doff = (uint32_t)(r * 64 + cp_ * 16);
        size_t soff = (size_t)(m0 + r) * Dd + k0 + c * 8;
        cp16(sdst + doff, Ah + soff);
        cp16(sdst + TILEB + doff, Al + soff);
    }
#pragma unroll
    for (int l = 0; l < 2; l++) {
        int e = tid + 256 * l;
        int r = e >> 2, c = e & 3;
        int cp_ = c ^ ((r >> 1) & 3);
        uint32_t doff = (uint32_t)(r * 64 + cp_ * 16);
        size_t soff = (size_t)(n0 + r) * Dd + k0 + c * 8;
        cp16(sdst + 2 * TILEB + doff, Bh + soff);
        cp16(sdst + 3 * TILEB + doff, Bl + soff);
    }
}

__device__ __forceinline__ void gemm_mainloop(
        uint32_t sbase,
        const __nv_bfloat16* __restrict__ Ah, const __nv_bfloat16* __restrict__ Al,
        const __nv_bfloat16* __restrict__ Bth, const __nv_bfloat16* __restrict__ Btl,
        int m0, int n0, float acc[4][4][4])
{
    const int lane = threadIdx.x & 31;
    const int wid  = threadIdx.x >> 5;
    const int wm = wid >> 2, wn = wid & 3;
    const int lr = lane & 7, g = lane >> 3;
    const int swz = (lr >> 1) & 3;
    const uint32_t arow = (uint32_t)((wm * 64 + (g & 1) * 8 + lr) * 64);
    const int akh = g >> 1;
    const uint32_t brow = (uint32_t)((wn * 32 + (g >> 1) * 8 + lr) * 64);
    const int bkh = g & 1;

    load_stage(sbase, Ah, Al, Bth, Btl, m0, n0, 0);
    CP_COMMIT();
    load_stage(sbase + STAGEB, Ah, Al, Bth, Btl, m0, n0, GBK);
    CP_COMMIT();

    const int NITER = Dd / GBK;   // 64
    int cur = 0;
    for (int it = 0; it < NITER; it++) {
        CP_WAIT1();
        __syncthreads();
        const uint32_t Sb = sbase + (uint32_t)cur * STAGEB;
        if (it + 2 < NITER) {
            int pf = cur + 2; if (pf >= 3) pf -= 3;
            load_stage(sbase + (uint32_t)pf * STAGEB, Ah, Al, Bth, Btl,
                       m0, n0, (it + 2) * GBK);
            CP_COMMIT();
        }
#pragma unroll
        for (int ks = 0; ks < 2; ks++) {
            const uint32_t ca = (uint32_t)(((ks * 2 + akh) ^ swz) * 16);
            const uint32_t cb = (uint32_t)(((ks * 2 + bkh) ^ swz) * 16);
            uint32_t ah[4][4], al[4][4];
#pragma unroll
            for (int i = 0; i < 4; i++) {
                ldsm_x4(ah[i], Sb + arow + (uint32_t)(i * 1024) + ca);
                ldsm_x4(al[i], Sb + TILEB + arow + (uint32_t)(i * 1024) + ca);
            }
#pragma unroll
            for (int jj = 0; jj < 2; jj++) {
                uint32_t bh4[4], bl4[4];
                ldsm_x4(bh4, Sb + 2 * TILEB + brow + (uint32_t)(jj * 1024) + cb);
                ldsm_x4(bl4, Sb + 3 * TILEB + brow + (uint32_t)(jj * 1024) + cb);
#pragma unroll
                for (int i = 0; i < 4; i++) {
                    mma_bf16(acc[i][2 * jj], ah[i], bh4[0], bh4[1]);
                    mma_bf16(acc[i][2 * jj], al[i], bh4[0], bh4[1]);
                    mma_bf16(acc[i][2 * jj], ah[i], bl4[0], bl4[1]);
                    mma_bf16(acc[i][2 * jj + 1], ah[i], bh4[2], bh4[3]);
                    mma_bf16(acc[i][2 * jj + 1], al[i], bh4[2], bh4[3]);
                    mma_bf16(acc[i][2 * jj + 1], ah[i], bl4[2], bl4[3]);
                }
            }
        }
        cur++; if (cur >= 3) cur = 0;
    }
}

// Fused QKV projection: gridDim.z selects q/k/v weight + epilogue.
__global__ __launch_bounds__(256, 2)
void gemm_qkv(const __nv_bfloat16* __restrict__ xh, const __nv_bfloat16* __restrict__ xl,
              const __nv_bfloat16* __restrict__ wth, const __nv_bfloat16* __restrict__ wtl,
              const float* __restrict__ bq, const float* __restrict__ bk,
              const float* __restrict__ bv)
{
    extern __shared__ char smem[];
    const uint32_t sbase = smem_u32(smem);
    const int z = blockIdx.z;
    const __nv_bfloat16* Bth = wth + (size_t)z * Dd * Dd;
    const __nv_bfloat16* Btl = wtl + (size_t)z * Dd * Dd;
    const float* bias = (z == 0) ? bq : (z == 1) ? bk : bv;
    const int m0 = blockIdx.y * GBM;
    const int n0 = blockIdx.x * GBN;

    float acc[4][4][4];
#pragma unroll
    for (int i = 0; i < 4; i++)
#pragma unroll
        for (int j = 0; j < 4; j++)
#pragma unroll
            for (int r = 0; r < 4; r++) acc[i][j][r] = 0.f;

    gemm_mainloop(sbase, xh, xl, Bth, Btl, m0, n0, acc);

    const int lane = threadIdx.x & 31;
    const int wid  = threadIdx.x >> 5;
    const int q4 = lane & 3, g8 = lane >> 2;
    const int wm = wid >> 2, wn = wid & 3;
    const int mbase = m0 + wm * 64;
#pragma unroll
    for (int j = 0; j < 4; j++) {
        const int nc = wn * 32 + j * 8 + 2 * q4;
        const float bx = bias[n0 + nc];
        const float by = bias[n0 + nc + 1];
#pragma unroll
        for (int i = 0; i < 4; i++) {
#pragma unroll
            for (int half = 0; half < 2; half++) {
                const int m = mbase + i * 16 + g8 + half * 8;
                float vx = acc[i][j][half * 2]     + bx;
                float vy = acc[i][j][half * 2 + 1] + by;
                const int h = n0 >> 7;
                const int b = m >> 11;
                const int t = m & 2047;
                if (z == 2) {
                    size_t base = ((size_t)(b * Hh + h) * DHd + nc) * Tt + t;
                    __nv_bfloat16 h0 = __float2bfloat16(vx);
                    __nv_bfloat16 h1 = __float2bfloat16(vy);
                    g_vth[base]       = h0;
                    g_vth[base + Tt]  = h1;
                    g_vtl[base]       = __float2bfloat16(vx - __bfloat162float(h0));
                    g_vtl[base + Tt]  = __float2bfloat16(vy - __bfloat162float(h1));
                } else {
                    __nv_bfloat16* dh = (z == 0) ? g_qh : g_kh;
                    __nv_bfloat16* dl = (z == 0) ? g_ql : g_kl;
                    size_t base = ((size_t)((b * Hh + h) * Tt) + t) * DHd + nc;
                    uint32_t hh, ll;
                    bf16_split2(vx, vy, hh, ll);
                    *(uint32_t*)(dh + base) = hh;
                    *(uint32_t*)(dl + base) = ll;
                }
            }
        }
    }
}

// Output projection: fp32 row-major result.
__global__ __launch_bounds__(256, 2)
void gemm_out(const __nv_bfloat16* __restrict__ Ah, const __nv_bfloat16* __restrict__ Al,
              const __nv_bfloat16* __restrict__ Bth, const __nv_bfloat16* __restrict__ Btl,
              const float* __restrict__ bias, float* __restrict__ Cout)
{
    extern __shared__ char smem[];
    const uint32_t sbase = smem_u32(smem);
    const int m0 = blockIdx.y * GBM;
    const int n0 = blockIdx.x * GBN;

    float acc[4][4][4];
#pragma unroll
    for (int i = 0; i < 4; i++)
#pragma unroll
        for (int j = 0; j < 4; j++)
#pragma unroll
            for (int r = 0; r < 4; r++) acc[i][j][r] = 0.f;

    gemm_mainloop(sbase, Ah, Al, Bth, Btl, m0, n0, acc);

    const int lane = threadIdx.x & 31;
    const int wid  = threadIdx.x >> 5;
    const int q4 = lane & 3, g8 = lane >> 2;
    const int wm = wid >> 2, wn = wid & 3;
    const int mbase = m0 + wm * 64;
#pragma unroll
    for (int j = 0; j < 4; j++) {
        const int nc = wn * 32 + j * 8 + 2 * q4;
        const float bx = bias[n0 + nc];
        const float by = bias[n0 + nc + 1];
#pragma unroll
        for (int i = 0; i < 4; i++) {
#pragma unroll
            for (int half = 0; half < 2; half++) {
                const int m = mbase + i * 16 + g8 + half * 8;
                *(float2*)(Cout + (size_t)m * Dd + n0 + nc) =
                    make_float2(acc[i][j][half * 2] + bx, acc[i][j][half * 2 + 1] + by);
            }
        }
    }
}

// ===========================================================================
// Flash attention (causal), bf16 hi/lo, 3-pass MMA, online softmax.
// BM=64 (4 warps x 16 rows), BN=64, DH=128, 128 threads, 2 CTAs/SM.
// Q lives in registers (staged once via the V area). K and V single-buffered;
// cross-CTA overlap hides load latency and softmax tensor-idle phases.
// ===========================================================================
#define FBM 64
#define FBN 64
#define FTHREADS 128
#define F_KH   0u          // Kh 64x272 = 17408 ; Kl at +17408
#define F_KLO  17408u
#define F_VH   34816u      // Vh 128x144 = 18432 ; Vl at +18432
#define F_VLO  18432u
#define F_PH   71680u      // Ph 64x144 = 9216 ; Pl at +9216
#define F_PLO  9216u
#define FLASH_SMEM 90112   // 2 CTAs/SM

// 64 rows x 128 bf16 (hi at dst, lo at dst + F_KLO), pitch 272B
__device__ __forceinline__ void flash_load_64x128(uint32_t dst,
        const __nv_bfloat16* __restrict__ ph, const __nv_bfloat16* __restrict__ pl) {
    const int tid = threadIdx.x;
#pragma unroll
    for (int l = 0; l < 8; l++) {
        int e = tid + l * FTHREADS;
        int r = e >> 4, c = e & 15;
        uint32_t doff = (uint32_t)(r * 272 + c * 16);
        cp16(dst + doff, ph + r * 128 + c * 8);
        cp16(dst + F_KLO + doff, pl + r * 128 + c * 8);
    }
}
// V tile: 128 d-rows x 64 t-cols (hi at dst, lo at dst + F_VLO), pitch 144B
__device__ __forceinline__ void flash_load_v(uint32_t dst,
        const __nv_bfloat16* __restrict__ vh, const __nv_bfloat16* __restrict__ vl) {
    const int tid = threadIdx.x;
#pragma unroll
    for (int l = 0; l < 8; l++) {
        int e = tid + l * FTHREADS;
        int r = e >> 3, c = e & 7;
        uint32_t doff = (uint32_t)(r * 144 + c * 16);
        cp16(dst + doff, vh + (size_t)r * Tt + c * 8);
        cp16(dst + F_VLO + doff, vl + (size_t)r * Tt + c * 8);
    }
}

__global__ __launch_bounds__(FTHREADS, 2)
void flash_tc()
{
    extern __shared__ char smc[];
    const uint32_t sb = smem_u32(smc);
    const int qb = (gridDim.x - 1) - blockIdx.x;    // longest-job-first
    const int h  = blockIdx.y;
    const int b  = blockIdx.z;
    const int q0 = qb * FBM;
    const int tid  = threadIdx.x;
    const int w    = tid >> 5;
    const int lane = tid & 31;
    const int q4   = lane & 3;
    const int rl   = lane >> 2;
    const int lr   = lane & 7;
    const int g    = lane >> 3;

    uint32_t* Ph32 = (uint32_t*)(smc + F_PH);
    uint32_t* Pl32 = (uint32_t*)(smc + F_PH + F_PLO);

    const uint32_t kAddr = sb + F_KH + (uint32_t)(((g >> 1) * 8 + lr) * 272 + (g & 1) * 16);
    const uint32_t pAddr = sb + F_PH + (uint32_t)((w * 16 + (g & 1) * 8 + lr) * 144 + (g >> 1) * 16);
    const uint32_t vAddr = sb + F_VH + (uint32_t)(((g >> 1) * 8 + lr) * 144 + (g & 1) * 16);

    const size_t bh = (size_t)(b * Hh + h) * Tt;
    const __nv_bfloat16* kbh = g_kh + bh * DHd;
    const __nv_bfloat16* kbl = g_kl + bh * DHd;
    const __nv_bfloat16* vbh = g_vth + (size_t)(b * Hh + h) * DHd * Tt;
    const __nv_bfloat16* vbl = g_vtl + (size_t)(b * Hh + h) * DHd * Tt;

    // --- Stage Q through the V area, then hold it in registers ---
    flash_load_64x128(sb + F_VH, g_qh + (bh + q0) * DHd, g_ql + (bh + q0) * DHd);
    CP_COMMIT();
    CP_WAIT0();
    __syncthreads();
    uint32_t qah[8][4], qal[8][4];
    {
        const uint32_t qAddr = sb + F_VH +
            (uint32_t)((w * 16 + (g & 1) * 8 + lr) * 272 + (g >> 1) * 16);
#pragma unroll
        for (int ks = 0; ks < 8; ks++) {
            ldsm_x4(qah[ks], qAddr + (uint32_t)(ks * 32));
            ldsm_x4(qal[ks], qAddr + F_KLO + (uint32_t)(ks * 32));
        }
    }
    __syncthreads();

    // Kick off K(0), V(0)
    flash_load_64x128(sb + F_KH, kbh, kbl);
    flash_load_v(sb + F_VH, vbh, vbl);
    CP_COMMIT();

    float m_lo = -1e30f, m_hi = -1e30f, l_lo = 0.f, l_hi = 0.f;
    float o[16][4];
#pragma unroll
    for (int nt = 0; nt < 16; nt++)
#pragma unroll
        for (int r = 0; r < 4; r++) o[nt][r] = 0.f;

    const int rowbase = q0 + w * 16;
    const int nkt = qb + 1;

    for (int t = 0; t < nkt; t++) {
        const int k0 = t * FBN;
        CP_WAIT0();            // K_t and V_t ready
        __syncthreads();

        // S = Q K^T (Q from registers)
        float sacc[8][4];
#pragma unroll
        for (int j = 0; j < 8; j++)
#pragma unroll
            for (int r = 0; r < 4; r++) sacc[j][r] = 0.f;

#pragma unroll
        for (int ks = 0; ks < 8; ks++) {
#pragma unroll
            for (int jj = 0; jj < 4; jj++) {
                uint32_t bh4[4], bl4[4];
                ldsm_x4(bh4, kAddr + (uint32_t)(jj * 4352 + ks * 32));
                ldsm_x4(bl4, kAddr + F_KLO + (uint32_t)(jj * 4352 + ks * 32));
                mma_bf16(sacc[2 * jj], qah[ks], bh4[0], bh4[1]);
                mma_bf16(sacc[2 * jj], qal[ks], bh4[0], bh4[1]);
                mma_bf16(sacc[2 * jj], qah[ks], bl4[0], bl4[1]);
                mma_bf16(sacc[2 * jj + 1], qah[ks], bh4[2], bh4[3]);
                mma_bf16(sacc[2 * jj + 1], qal[ks], bh4[2], bh4[3]);
                mma_bf16(sacc[2 * jj + 1], qah[ks], bl4[2], bl4[3]);
            }
        }

        __syncthreads();       // all warps done reading K_t
        if (t + 1 < nkt) {
            flash_load_64x128(sb + F_KH, kbh + (size_t)(t + 1) * FBN * DHd,
                              kbl + (size_t)(t + 1) * FBN * DHd);
            CP_COMMIT();
        }

        // Causal mask + online softmax
        {
            const int R_lo = rowbase + rl;
            const int R_hi = R_lo + 8;
            const bool needmask = (k0 + FBN - 1) > rowbase;
            float tl = -1e30f, th = -1e30f;
#pragma unroll
            for (int j = 0; j < 8; j++) {
#pragma unroll
                for (int r = 0; r < 4; r++) sacc[j][r] *= SCALE;
                if (needmask) {
                    const int C = k0 + j * 8 + 2 * q4;
                    if (C > R_lo)     sacc[j][0] = -1e30f;
                    if (C + 1 > R_lo) sacc[j][1] = -1e30f;
                    if (C > R_hi)     sacc[j][2] = -1e30f;
                    if (C + 1 > R_hi) sacc[j][3] = -1e30f;
                }
                tl = fmaxf(tl, fmaxf(sacc[j][0], sacc[j][1]));
                th = fmaxf(th, fmaxf(sacc[j][2], sacc[j][3]));
            }
            tl = fmaxf(tl, __shfl_xor_sync(0xffffffffu, tl, 1));
            tl = fmaxf(tl, __shfl_xor_sync(0xffffffffu, tl, 2));
            th = fmaxf(th, __shfl_xor_sync(0xffffffffu, th, 1));
            th = fmaxf(th, __shfl_xor_sync(0xffffffffu, th, 2));

            const float mn_lo = fmaxf(m_lo, tl);
            const float mn_hi = fmaxf(m_hi, th);
            const float a_lo = __expf(m_lo - mn_lo);
            const float a_hi = __expf(m_hi - mn_hi);
            m_lo = mn_lo; m_hi = mn_hi;

            float sum_lo = 0.f, sum_hi = 0.f;
            uint32_t* prl_h = Ph32 + (w * 16 + rl) * 36;
            uint32_t* prl_l = Pl32 + (w * 16 + rl) * 36;
#pragma unroll
            for (int j = 0; j < 8; j++) {
                float p0 = __expf(sacc[j][0] - mn_lo);
                float p1 = __expf(sacc[j][1] - mn_lo);
                float p2 = __expf(sacc[j][2] - mn_hi);
                float p3 = __expf(sacc[j][3] - mn_hi);
                sum_lo += p0 + p1;
                sum_hi += p2 + p3;
                uint32_t hh, ll;
                bf16_split2(p0, p1, hh, ll);
                prl_h[j * 4 + q4] = hh;
                prl_l[j * 4 + q4] = ll;
                bf16_split2(p2, p3, hh, ll);
                prl_h[8 * 36 + j * 4 + q4] = hh;
                prl_l[8 * 36 + j * 4 + q4] = ll;
            }
            sum_lo += __shfl_xor_sync(0xffffffffu, sum_lo, 1);
            sum_lo += __shfl_xor_sync(0xffffffffu, sum_lo, 2);
            sum_hi += __shfl_xor_sync(0xffffffffu, sum_hi, 1);
            sum_hi += __shfl_xor_sync(0xffffffffu, sum_hi, 2);
            l_lo = l_lo * a_lo + sum_lo;
            l_hi = l_hi * a_hi + sum_hi;

#pragma unroll
            for (int nt = 0; nt < 16; nt++) {
                o[nt][0] *= a_lo; o[nt][1] *= a_lo;
                o[nt][2] *= a_hi; o[nt][3] *= a_hi;
            }
            __syncwarp();

            // O += P @ V  (3-pass bf16)
#pragma unroll
            for (int ks = 0; ks < 4; ks++) {
                uint32_t ph4[4], pl4[4];
                ldsm_x4(ph4, pAddr + (uint32_t)(ks * 32));
                ldsm_x4(pl4, pAddr + F_PLO + (uint32_t)(ks * 32));
#pragma unroll
                for (int ntp = 0; ntp < 8; ntp++) {
                    uint32_t vh4[4], vl4[4];
                    ldsm_x4(vh4, vAddr + (uint32_t)(ntp * 2304 + ks * 32));
                    ldsm_x4(vl4, vAddr + F_VLO + (uint32_t)(ntp * 2304 + ks * 32));
                    mma_bf16(o[2 * ntp], ph4, vh4[0], vh4[1]);
                    mma_bf16(o[2 * ntp], pl4, vh4[0], vh4[1]);
                    mma_bf16(o[2 * ntp], ph4, vl4[0], vl4[1]);
                    mma_bf16(o[2 * ntp + 1], ph4, vh4[2], vh4[3]);
                    mma_bf16(o[2 * ntp + 1], pl4, vh4[2], vh4[3]);
                    mma_bf16(o[2 * ntp + 1], ph4, vl4[2], vl4[3]);
                }
            }
        }
        __syncthreads();       // all warps done reading V_t
        if (t + 1 < nkt) {
            flash_load_v(sb + F_VH, vbh + (size_t)(t + 1) * FBN,
                         vbl + (size_t)(t + 1) * FBN);
            CP_COMMIT();
        }
    }

    // Epilogue: divide by l, split, write att hi/lo [B,T,D]
    const float il_lo = 1.f / l_lo;
    const float il_hi = 1.f / l_hi;
    __nv_bfloat16* oh = g_atth + ((size_t)(b * Tt + rowbase)) * Dd + h * DHd;
    __nv_bfloat16* ol = g_attl + ((size_t)(b * Tt + rowbase)) * Dd + h * DHd;
#pragma unroll
    for (int nt = 0; nt < 16; nt++) {
        uint32_t hh, ll;
        size_t idx0 = (size_t)rl * Dd + nt * 8 + 2 * q4;
        bf16_split2(o[nt][0] * il_lo, o[nt][1] * il_lo, hh, ll);
        *(uint32_t*)(oh + idx0) = hh;
        *(uint32_t*)(ol + idx0) = ll;
        size_t idx1 = (size_t)(rl + 8) * Dd + nt * 8 + 2 * q4;
        bf16_split2(o[nt][2] * il_hi, o[nt][3] * il_hi, hh, ll);
        *(uint32_t*)(oh + idx1) = hh;
        *(uint32_t*)(ol + idx1) = ll;
    }
}

// ===========================================================================
extern "C" void kernel_launch(void* const* d_in, const int* in_sizes, int n_in,
                              void* d_out, int out_size)
{
    const float* x  = (const float*)d_in[0];
    const float* Wq = (const float*)d_in[1];
    const float* bq = (const float*)d_in[2];
    const float* Wk = (const float*)d_in[3];
    const float* bk = (const float*)d_in[4];
    const float* Wv = (const float*)d_in[5];
    const float* bv = (const float*)d_in[6];
    const float* Wo = (const float*)d_in[7];
    const float* bo = (const float*)d_in[8];
    float* out = (float*)d_out;

    __nv_bfloat16 *xh, *xl, *wth, *wtl, *atth, *attl;
    cudaGetSymbolAddress((void**)&xh,   g_xh);
    cudaGetSymbolAddress((void**)&xl,   g_xl);
    cudaGetSymbolAddress((void**)&wth,  g_wth);
    cudaGetSymbolAddress((void**)&wtl,  g_wtl);
    cudaGetSymbolAddress((void**)&atth, g_atth);
    cudaGetSymbolAddress((void**)&attl, g_attl);

    // 1) Convert inputs to bf16 hi/lo (x natural, all 4 W transposed, fused)
    conv_x_kernel<<<(Mm * Dd) / 1024, 256>>>(x, xh, xl);
    dim3 wgrid(Dd / 32, Dd / 32, 4);
    conv_w_all<<<wgrid, dim3(32, 8)>>>(Wq, Wk, Wv, Wo, wth, wtl);

    cudaFuncSetAttribute(gemm_qkv, cudaFuncAttributeMaxDynamicSharedMemorySize, GEMM_SMEM);
    cudaFuncSetAttribute(gemm_out, cudaFuncAttributeMaxDynamicSharedMemorySize, GEMM_SMEM);

    // 2) Fused QKV projections (one launch, one tail)
    dim3 qkvgrid(Dd / GBN, Mm / GBM, 3);   // (16, 64, 3)
    gemm_qkv<<<qkvgrid, 256, GEMM_SMEM>>>(xh, xl, wth, wtl, bq, bk, bv);

    // 3) Flash attention (BM=64, 128 threads, 2 CTAs/SM)
    cudaFuncSetAttribute(flash_tc, cudaFuncAttributeMaxDynamicSharedMemorySize, FLASH_SMEM);
    dim3 fgrid(Tt / FBM, Hh, Bq);          // (32, 16, 4)
    flash_tc<<<fgrid, FTHREADS, FLASH_SMEM>>>();

    // 4) Output projection (fp32 out)
    dim3 ogrid(Dd / GBN, Mm / GBM);        // (16, 64)
    gemm_out<<<ogrid, 256, GEMM_SMEM>>>(atth, attl, wth + 3 * (size_t)Dd * Dd,
                                        wtl + 3 * (size_t)Dd * Dd, bo, out);
}

// round 15
// speedup vs baseline: 1.0578x; 1.0578x over previous
#include <cuda_runtime.h>
#include <cuda_bf16.h>
#include <math_constants.h>
#include <cstdint>

#define Bq  4
#define Tt  2048
#define Dd  2048
#define Hh  16
#define DHd 128
#define Mm  (Bq * Tt)        // 8192
#define SCALE 0.08838834764831845f  // DH^-0.5

// ---------------------------------------------------------------------------
// Persistent bf16 hi/lo tensors (allocation-free rule: __device__ globals)
// ---------------------------------------------------------------------------
__device__ __align__(256) __nv_bfloat16 g_xh[Mm * Dd];
__device__ __align__(256) __nv_bfloat16 g_xl[Mm * Dd];
__device__ __align__(256) __nv_bfloat16 g_wth[4][Dd * Dd];   // W^T hi, [N][K]
__device__ __align__(256) __nv_bfloat16 g_wtl[4][Dd * Dd];   // W^T lo
__device__ __align__(256) __nv_bfloat16 g_qh[Bq * Hh * Tt * DHd];
__device__ __align__(256) __nv_bfloat16 g_ql[Bq * Hh * Tt * DHd];
__device__ __align__(256) __nv_bfloat16 g_kh[Bq * Hh * Tt * DHd];
__device__ __align__(256) __nv_bfloat16 g_kl[Bq * Hh * Tt * DHd];
__device__ __align__(256) __nv_bfloat16 g_vth[Bq * Hh * DHd * Tt];  // [b,h,d,t]
__device__ __align__(256) __nv_bfloat16 g_vtl[Bq * Hh * DHd * Tt];
__device__ __align__(256) __nv_bfloat16 g_atth[Bq * Tt * Dd];
__device__ __align__(256) __nv_bfloat16 g_attl[Bq * Tt * Dd];

// ===========================================================================
// Helpers
// ===========================================================================
__device__ __forceinline__ uint32_t smem_u32(const void* p) {
    uint32_t a;
    asm("{ .reg .u64 t; cvta.to.shared.u64 t, %1; cvt.u32.u64 %0, t; }" : "=r"(a) : "l"(p));
    return a;
}
__device__ __forceinline__ void cp16(uint32_t dst, const void* src) {
    asm volatile("cp.async.cg.shared.global [%0], [%1], 16;" :: "r"(dst), "l"(src));
}
#define CP_COMMIT() asm volatile("cp.async.commit_group;" ::: "memory")
#define CP_WAIT0()  asm volatile("cp.async.wait_group 0;" ::: "memory")
#define CP_WAIT1()  asm volatile("cp.async.wait_group 1;" ::: "memory")

__device__ __forceinline__ void mma_bf16(float* c, const uint32_t* a,
                                         uint32_t b0, uint32_t b1) {
    asm volatile(
        "mma.sync.aligned.m16n8k16.row.col.f32.bf16.bf16.f32 "
        "{%0,%1,%2,%3}, {%4,%5,%6,%7}, {%8,%9}, {%0,%1,%2,%3};"
        : "+f"(c[0]), "+f"(c[1]), "+f"(c[2]), "+f"(c[3])
        : "r"(a[0]), "r"(a[1]), "r"(a[2]), "r"(a[3]), "r"(b0), "r"(b1));
}
__device__ __forceinline__ void ldsm_x4(uint32_t* r, uint32_t addr) {
    asm volatile("ldmatrix.sync.aligned.m8n8.x4.shared.b16 {%0,%1,%2,%3}, [%4];"
        : "=r"(r[0]), "=r"(r[1]), "=r"(r[2]), "=r"(r[3]) : "r"(addr));
}
__device__ __forceinline__ uint32_t pack_bf16(float v0, float v1) {
    uint32_t h;
    asm("cvt.rn.bf16x2.f32 %0, %1, %2;" : "=r"(h) : "f"(v1), "f"(v0));
    return h;
}
// Split pair of fp32 into bf16x2 hi + bf16x2 residual (lower 16 bits = v0)
__device__ __forceinline__ void bf16_split2(float v0, float v1,
                                            uint32_t& hi, uint32_t& lo) {
    uint32_t h = pack_bf16(v0, v1);
    float f0 = __uint_as_float(h << 16);
    float f1 = __uint_as_float(h & 0xffff0000u);
    lo = pack_bf16(v0 - f0, v1 - f1);
    hi = h;
}

// ===========================================================================
// Conversion kernels
// ===========================================================================
__global__ __launch_bounds__(256)
void conv_x_kernel(const float* __restrict__ src,
                   __nv_bfloat16* __restrict__ hi, __nv_bfloat16* __restrict__ lo)
{
    const size_t i4 = ((size_t)blockIdx.x * 256 + threadIdx.x) * 4;
    float4 v = *(const float4*)(src + i4);
    uint32_t h0, l0, h1, l1;
    bf16_split2(v.x, v.y, h0, l0);
    bf16_split2(v.z, v.w, h1, l1);
    *(uint2*)(hi + i4) = make_uint2(h0, h1);
    *(uint2*)(lo + i4) = make_uint2(l0, l1);
}

// Transpose all 4 W [K][N] -> W^T [N][K], split to bf16 hi/lo. gridDim.z = 4.
__global__ __launch_bounds__(256)
void conv_w_all(const float* __restrict__ W0, const float* __restrict__ W1,
                const float* __restrict__ W2, const float* __restrict__ W3,
                __nv_bfloat16* __restrict__ Th, __nv_bfloat16* __restrict__ Tl)
{
    const int z = blockIdx.z;
    const float* W = (z == 0) ? W0 : (z == 1) ? W1 : (z == 2) ? W2 : W3;
    __nv_bfloat16* th = Th + (size_t)z * Dd * Dd;
    __nv_bfloat16* tl = Tl + (size_t)z * Dd * Dd;

    __shared__ float tile[32][33];
    int x = blockIdx.x * 32 + threadIdx.x;
    int y = blockIdx.y * 32 + threadIdx.y;
#pragma unroll
    for (int j = 0; j < 32; j += 8)
        tile[threadIdx.y + j][threadIdx.x] = W[(size_t)(y + j) * Dd + x];
    __syncthreads();
    int n = blockIdx.x * 32 + threadIdx.y;
    int k = blockIdx.y * 32 + threadIdx.x;
#pragma unroll
    for (int j = 0; j < 32; j += 8) {
        float v = tile[threadIdx.x][threadIdx.y + j];
        __nv_bfloat16 h = __float2bfloat16(v);
        __nv_bfloat16 l = __float2bfloat16(v - __bfloat162float(h));
        th[(size_t)(n + j) * Dd + k] = h;
        tl[(size_t)(n + j) * Dd + k] = l;
    }
}

// ===========================================================================
// bf16 hi/lo tensor-core GEMM core (R11 config: best measured).
// BM=BN=128, BK=32, 256 threads (8 warps 2x4), warp tile 64x32.
// 3-stage cp.async ring (96KB) at 2 CTAs/SM. Dense 64B rows + XOR swizzle.
// ===========================================================================
#define GBM 128
#define GBN 128
#define GBK 32
#define TILEB 8192                    // 128 rows * 64B
#define STAGEB (4 * TILEB)            // 32768: Ah|Al|Bh|Bl
#define GEMM_SMEM (3 * STAGEB)        // 98304 -> 2 CTAs/SM

__device__ __forceinline__ void load_stage(uint32_t sdst,
        const __nv_bfloat16* __restrict__ Ah, const __nv_bfloat16* __restrict__ Al,
        const __nv_bfloat16* __restrict__ Bh, const __nv_bfloat16* __restrict__ Bl,
        int m0, int n0, int k0)
{
    const int tid = threadIdx.x;
#pragma unroll
    for (int l = 0; l < 2; l++) {
        int e = tid + 256 * l;
        int r = e >> 2, c = e & 3;
        int cp_ = c ^ ((r >> 1) & 3);
        uint32_t doff = (uint32_t)(r * 64 + cp_ * 16);
        size_t soff = (size_t)(m0 + r) * Dd + k0 + c * 8;
        cp16(sdst + doff, Ah + soff);
        cp16(sdst + TILEB + doff, Al + soff);
    }
#pragma unroll
    for (int l = 0; l < 2; l++) {
        int e = tid + 256 * l;
        int r = e >> 2, c = e & 3;
        int cp_ = c ^ ((r >> 1) & 3);
        uint32_t doff = (uint32_t)(r * 64 + cp_ * 16);
        size_t soff = (size_t)(n0 + r) * Dd + k0 + c * 8;
        cp16(sdst + 2 * TILEB + doff, Bh + soff);
        cp16(sdst + 3 * TILEB + doff, Bl + soff);
    }
}

__device__ __forceinline__ void gemm_mainloop(
        uint32_t sbase,
        const __nv_bfloat16* __restrict__ Ah, const __nv_bfloat16* __restrict__ Al,
        const __nv_bfloat16* __restrict__ Bth, const __nv_bfloat16* __restrict__ Btl,
        int m0, int n0, float acc[4][4][4])
{
    const int lane = threadIdx.x & 31;
    const int wid  = threadIdx.x >> 5;
    const int wm = wid >> 2, wn = wid & 3;
    const int lr = lane & 7, g = lane >> 3;
    const int swz = (lr >> 1) & 3;
    const uint32_t arow = (uint32_t)((wm * 64 + (g & 1) * 8 + lr) * 64);
    const int akh = g >> 1;
    const uint32_t brow = (uint32_t)((wn * 32 + (g >> 1) * 8 + lr) * 64);
    const int bkh = g & 1;

    load_stage(sbase, Ah, Al, Bth, Btl, m0, n0, 0);
    CP_COMMIT();
    load_stage(sbase + STAGEB, Ah, Al, Bth, Btl, m0, n0, GBK);
    CP_COMMIT();

    const int NITER = Dd / GBK;   // 64
    int cur = 0;
    for (int it = 0; it < NITER; it++) {
        if (it == NITER - 1) { CP_WAIT0(); } else { CP_WAIT1(); }
        __syncthreads();
        const uint32_t Sb = sbase + (uint32_t)cur * STAGEB;
        if (it + 2 < NITER) {
            int pf = cur + 2; if (pf >= 3) pf -= 3;
            load_stage(sbase + (uint32_t)pf * STAGEB, Ah, Al, Bth, Btl,
                       m0, n0, (it + 2) * GBK);
            CP_COMMIT();
        }
#pragma unroll
        for (int ks = 0; ks < 2; ks++) {
            const uint32_t ca = (uint32_t)(((ks * 2 + akh) ^ swz) * 16);
            const uint32_t cb = (uint32_t)(((ks * 2 + bkh) ^ swz) * 16);
            uint32_t ah[4][4], al[4][4];
#pragma unroll
            for (int i = 0; i < 4; i++) {
                ldsm_x4(ah[i], Sb + arow + (uint32_t)(i * 1024) + ca);
                ldsm_x4(al[i], Sb + TILEB + arow + (uint32_t)(i * 1024) + ca);
            }
#pragma unroll
            for (int jj = 0; jj < 2; jj++) {
                uint32_t bh4[4], bl4[4];
                ldsm_x4(bh4, Sb + 2 * TILEB + brow + (uint32_t)(jj * 1024) + cb);
                ldsm_x4(bl4, Sb + 3 * TILEB + brow + (uint32_t)(jj * 1024) + cb);
#pragma unroll
                for (int i = 0; i < 4; i++) {
                    mma_bf16(acc[i][2 * jj], ah[i], bh4[0], bh4[1]);
                    mma_bf16(acc[i][2 * jj], al[i], bh4[0], bh4[1]);
                    mma_bf16(acc[i][2 * jj], ah[i], bl4[0], bl4[1]);
                    mma_bf16(acc[i][2 * jj + 1], ah[i], bh4[2], bh4[3]);
                    mma_bf16(acc[i][2 * jj + 1], al[i], bh4[2], bh4[3]);
                    mma_bf16(acc[i][2 * jj + 1], ah[i], bl4[2], bl4[3]);
                }
            }
        }
        cur++; if (cur >= 3) cur = 0;
    }
}

// Fused QKV projection: gridDim.z selects q/k/v weight + epilogue.
__global__ __launch_bounds__(256, 2)
void gemm_qkv(const __nv_bfloat16* __restrict__ xh, const __nv_bfloat16* __restrict__ xl,
              const __nv_bfloat16* __restrict__ wth, const __nv_bfloat16* __restrict__ wtl,
              const float* __restrict__ bq, const float* __restrict__ bk,
              const float* __restrict__ bv)
{
    extern __shared__ char smem[];
    const uint32_t sbase = smem_u32(smem);
    const int z = blockIdx.z;
    const __nv_bfloat16* Bth = wth + (size_t)z * Dd * Dd;
    const __nv_bfloat16* Btl = wtl + (size_t)z * Dd * Dd;
    const float* bias = (z == 0) ? bq : (z == 1) ? bk : bv;
    const int m0 = blockIdx.y * GBM;
    const int n0 = blockIdx.x * GBN;

    float acc[4][4][4];
#pragma unroll
    for (int i = 0; i < 4; i++)
#pragma unroll
        for (int j = 0; j < 4; j++)
#pragma unroll
            for (int r = 0; r < 4; r++) acc[i][j][r] = 0.f;

    gemm_mainloop(sbase, xh, xl, Bth, Btl, m0, n0, acc);

    const int lane = threadIdx.x & 31;
    const int wid  = threadIdx.x >> 5;
    const int q4 = lane & 3, g8 = lane >> 2;
    const int wm = wid >> 2, wn = wid & 3;
    const int mbase = m0 + wm * 64;
#pragma unroll
    for (int j = 0; j < 4; j++) {
        const int nc = wn * 32 + j * 8 + 2 * q4;
        const float bx = bias[n0 + nc];
        const float by = bias[n0 + nc + 1];
#pragma unroll
        for (int i = 0; i < 4; i++) {
#pragma unroll
            for (int half = 0; half < 2; half++) {
                const int m = mbase + i * 16 + g8 + half * 8;
                float vx = acc[i][j][half * 2]     + bx;
                float vy = acc[i][j][half * 2 + 1] + by;
                const int h = n0 >> 7;
                const int b = m >> 11;
                const int t = m & 2047;
                if (z == 2) {
                    size_t base = ((size_t)(b * Hh + h) * DHd + nc) * Tt + t;
                    __nv_bfloat16 h0 = __float2bfloat16(vx);
                    __nv_bfloat16 h1 = __float2bfloat16(vy);
                    g_vth[base]       = h0;
                    g_vth[base + Tt]  = h1;
                    g_vtl[base]       = __float2bfloat16(vx - __bfloat162float(h0));
                    g_vtl[base + Tt]  = __float2bfloat16(vy - __bfloat162float(h1));
                } else {
                    __nv_bfloat16* dh = (z == 0) ? g_qh : g_kh;
                    __nv_bfloat16* dl = (z == 0) ? g_ql : g_kl;
                    size_t base = ((size_t)((b * Hh + h) * Tt) + t) * DHd + nc;
                    uint32_t hh, ll;
                    bf16_split2(vx, vy, hh, ll);
                    *(uint32_t*)(dh + base) = hh;
                    *(uint32_t*)(dl + base) = ll;
                }
            }
        }
    }
}

// Output projection: fp32 row-major result.
__global__ __launch_bounds__(256, 2)
void gemm_out(const __nv_bfloat16* __restrict__ Ah, const __nv_bfloat16* __restrict__ Al,
              const __nv_bfloat16* __restrict__ Bth, const __nv_bfloat16* __restrict__ Btl,
              const float* __restrict__ bias, float* __restrict__ Cout)
{
    extern __shared__ char smem[];
    const uint32_t sbase = smem_u32(smem);
    const int m0 = blockIdx.y * GBM;
    const int n0 = blockIdx.x * GBN;

    float acc[4][4][4];
#pragma unroll
    for (int i = 0; i < 4; i++)
#pragma unroll
        for (int j = 0; j < 4; j++)
#pragma unroll
            for (int r = 0; r < 4; r++) acc[i][j][r] = 0.f;

    gemm_mainloop(sbase, Ah, Al, Bth, Btl, m0, n0, acc);

    const int lane = threadIdx.x & 31;
    const int wid  = threadIdx.x >> 5;
    const int q4 = lane & 3, g8 = lane >> 2;
    const int wm = wid >> 2, wn = wid & 3;
    const int mbase = m0 + wm * 64;
#pragma unroll
    for (int j = 0; j < 4; j++) {
        const int nc = wn * 32 + j * 8 + 2 * q4;
        const float bx = bias[n0 + nc];
        const float by = bias[n0 + nc + 1];
#pragma unroll
        for (int i = 0; i < 4; i++) {
#pragma unroll
            for (int half = 0; half < 2; half++) {
                const int m = mbase + i * 16 + g8 + half * 8;
                *(float2*)(Cout + (size_t)m * Dd + n0 + nc) =
                    make_float2(acc[i][j][half * 2] + bx, acc[i][j][half * 2 + 1] + by);
            }
        }
    }
}

// ===========================================================================
// Flash attention (causal), bf16 hi/lo, 3-pass MMA, online softmax.
// BM=128, BN=64, DH=128, 256 threads, 1 CTA/SM.
// Warp grid 4(M)x2(N): warp = 32 rows x 32 S-cols, PV d-half per wc.
// Cross-warp softmax combine via smem smax/ssum. K single-, V double-buffered.
// ===========================================================================
#define FBM 128
#define FBN 64
#define F_QH   0u
#define F_QL   34816u
#define F_KH   69632u
#define F_KL   87040u
#define F_V0H  104448u
#define F_VLO  18432u      // lo offset within a V buffer
#define F_VSTR 36864u      // stride between V buffers
#define F_PH   178176u
#define F_PL   196608u
#define F_RED  215040u     // smax[2][128] | ssum[2][128]
#define FLASH_SMEM 217088

__device__ __forceinline__ void flash_load_q(uint32_t sb,
        const __nv_bfloat16* __restrict__ qh, const __nv_bfloat16* __restrict__ ql) {
    const int tid = threadIdx.x;
#pragma unroll
    for (int l = 0; l < 8; l++) {
        int e = tid + l * 256;
        int r = e >> 4, c = e & 15;
        uint32_t doff = (uint32_t)(r * 272 + c * 16);
        cp16(sb + F_QH + doff, qh + r * 128 + c * 8);
        cp16(sb + F_QL + doff, ql + r * 128 + c * 8);
    }
}
__device__ __forceinline__ void flash_load_k(uint32_t sb,
        const __nv_bfloat16* __restrict__ kh, const __nv_bfloat16* __restrict__ kl) {
    const int tid = threadIdx.x;
#pragma unroll
    for (int l = 0; l < 4; l++) {
        int e = tid + l * 256;
        int r = e >> 4, c = e & 15;
        uint32_t doff = (uint32_t)(r * 272 + c * 16);
        cp16(sb + F_KH + doff, kh + r * 128 + c * 8);
        cp16(sb + F_KL + doff, kl + r * 128 + c * 8);
    }
}
__device__ __forceinline__ void flash_load_v(uint32_t dsth,
        const __nv_bfloat16* __restrict__ vh, const __nv_bfloat16* __restrict__ vl) {
    const int tid = threadIdx.x;
#pragma unroll
    for (int l = 0; l < 4; l++) {
        int e = tid + l * 256;
        int r = e >> 3, c = e & 7;
        uint32_t doff = (uint32_t)(r * 144 + c * 16);
        cp16(dsth + doff, vh + (size_t)r * Tt + c * 8);
        cp16(dsth + F_VLO + doff, vl + (size_t)r * Tt + c * 8);
    }
}

__global__ __launch_bounds__(256, 1)
void flash_tc()
{
    extern __shared__ char smc[];
    const uint32_t sb = smem_u32(smc);
    const int qb = (gridDim.x - 1) - blockIdx.x;    // longest-job-first
    const int h  = blockIdx.y;
    const int b  = blockIdx.z;
    const int q0 = qb * FBM;
    const int tid  = threadIdx.x;
    const int w    = tid >> 5;
    const int lane = tid & 31;
    const int q4   = lane & 3;
    const int rl   = lane >> 2;
    const int lr   = lane & 7;
    const int g    = lane >> 3;
    const int wr   = w >> 1;      // 0..3 (32-row group)
    const int wc   = w & 1;       // 0..1 (col half)

    uint32_t* Ph32 = (uint32_t*)(smc + F_PH);
    uint32_t* Pl32 = (uint32_t*)(smc + F_PL);
    float* smax = (float*)(smc + F_RED);            // [2][128]
    float* ssum = (float*)(smc + F_RED + 1024);     // [2][128]

    const uint32_t qAddr = sb + F_QH + (uint32_t)((wr * 32 + (g & 1) * 8 + lr) * 272 + (g >> 1) * 16);
    const uint32_t kAddr = sb + F_KH + (uint32_t)((wc * 32 + (g >> 1) * 8 + lr) * 272 + (g & 1) * 16);
    const uint32_t pAddr = sb + F_PH + (uint32_t)((wr * 32 + (g & 1) * 8 + lr) * 144 + (g >> 1) * 16);
    const uint32_t vAddrOff = (uint32_t)((wc * 64 + (g >> 1) * 8 + lr) * 144 + (g & 1) * 16);

    const size_t bh = (size_t)(b * Hh + h) * Tt;
    const __nv_bfloat16* kbh = g_kh + bh * DHd;
    const __nv_bfloat16* kbl = g_kl + bh * DHd;
    const __nv_bfloat16* vbh = g_vth + (size_t)(b * Hh + h) * DHd * Tt;
    const __nv_bfloat16* vbl = g_vtl + (size_t)(b * Hh + h) * DHd * Tt;

    flash_load_q(sb, g_qh + (bh + q0) * DHd, g_ql + (bh + q0) * DHd);
    flash_load_k(sb, kbh, kbl);
    flash_load_v(sb + F_V0H, vbh, vbl);
    CP_COMMIT();

    float mst[2][2], lst[2][2];
#pragma unroll
    for (int i = 0; i < 2; i++)
#pragma unroll
        for (int hf = 0; hf < 2; hf++) { mst[i][hf] = -1e30f; lst[i][hf] = 0.f; }
    float o[2][8][4];
#pragma unroll
    for (int i = 0; i < 2; i++)
#pragma unroll
        for (int nt = 0; nt < 8; nt++)
#pragma unroll
            for (int r = 0; r < 4; r++) o[i][nt][r] = 0.f;

    const int rowb = q0 + wr * 32;
    const int nkt = 2 * qb + 2;

    for (int t = 0; t < nkt; t++) {
        const int k0 = t * FBN;
        const bool active = (k0 <= rowb + 31);
        CP_WAIT0();            // K_t and V_t ready
        __syncthreads();       // B1

        if (t + 1 < nkt) {
            flash_load_v(sb + F_V0H + (uint32_t)((t + 1) & 1) * F_VSTR,
                         vbh + (size_t)(t + 1) * FBN, vbl + (size_t)(t + 1) * FBN);
            CP_COMMIT();
        }

        float sacc[2][4][4];
        float tmax[2][2];
        if (active) {
#pragma unroll
            for (int i = 0; i < 2; i++)
#pragma unroll
                for (int j = 0; j < 4; j++)
#pragma unroll
                    for (int r = 0; r < 4; r++) sacc[i][j][r] = 0.f;

#pragma unroll
            for (int ks = 0; ks < 8; ks++) {
                uint32_t a0h[4], a0l[4], a1h[4], a1l[4];
                ldsm_x4(a0h, qAddr + (uint32_t)(ks * 32));
                ldsm_x4(a0l, qAddr + (F_QL - F_QH) + (uint32_t)(ks * 32));
                ldsm_x4(a1h, qAddr + (uint32_t)(16 * 272 + ks * 32));
                ldsm_x4(a1l, qAddr + (F_QL - F_QH) + (uint32_t)(16 * 272 + ks * 32));
#pragma unroll
                for (int jj = 0; jj < 2; jj++) {
                    uint32_t bh4[4], bl4[4];
                    ldsm_x4(bh4, kAddr + (uint32_t)(jj * 16 * 272 + ks * 32));
                    ldsm_x4(bl4, kAddr + (F_KL - F_KH) + (uint32_t)(jj * 16 * 272 + ks * 32));
                    mma_bf16(sacc[0][2 * jj], a0h, bh4[0], bh4[1]);
                    mma_bf16(sacc[0][2 * jj], a0l, bh4[0], bh4[1]);
                    mma_bf16(sacc[0][2 * jj], a0h, bl4[0], bl4[1]);
                    mma_bf16(sacc[0][2 * jj + 1], a0h, bh4[2], bh4[3]);
                    mma_bf16(sacc[0][2 * jj + 1], a0l, bh4[2], bh4[3]);
                    mma_bf16(sacc[0][2 * jj + 1], a0h, bl4[2], bl4[3]);
                    mma_bf16(sacc[1][2 * jj], a1h, bh4[0], bh4[1]);
                    mma_bf16(sacc[1][2 * jj], a1l, bh4[0], bh4[1]);
                    mma_bf16(sacc[1][2 * jj], a1h, bl4[0], bl4[1]);
                    mma_bf16(sacc[1][2 * jj + 1], a1h, bh4[2], bh4[3]);
                    mma_bf16(sacc[1][2 * jj + 1], a1l, bh4[2], bh4[3]);
                    mma_bf16(sacc[1][2 * jj + 1], a1h, bl4[2], bl4[3]);
                }
            }

            // scale + causal mask + per-half partial row max
            const bool needmask = (k0 + FBN - 1) > rowb;
#pragma unroll
            for (int i = 0; i < 2; i++) {
                const int R_lo = rowb + 16 * i + rl;
                const int R_hi = R_lo + 8;
                float tl = -1e30f, th = -1e30f;
#pragma unroll
                for (int j = 0; j < 4; j++) {
#pragma unroll
                    for (int r = 0; r < 4; r++) sacc[i][j][r] *= SCALE;
                    if (needmask) {
                        const int C = k0 + wc * 32 + j * 8 + 2 * q4;
                        if (C > R_lo)     sacc[i][j][0] = -1e30f;
                        if (C + 1 > R_lo) sacc[i][j][1] = -1e30f;
                        if (C > R_hi)     sacc[i][j][2] = -1e30f;
                        if (C + 1 > R_hi) sacc[i][j][3] = -1e30f;
                    }
                    tl = fmaxf(tl, fmaxf(sacc[i][j][0], sacc[i][j][1]));
                    th = fmaxf(th, fmaxf(sacc[i][j][2], sacc[i][j][3]));
                }
                tl = fmaxf(tl, __shfl_xor_sync(0xffffffffu, tl, 1));
                tl = fmaxf(tl, __shfl_xor_sync(0xffffffffu, tl, 2));
                th = fmaxf(th, __shfl_xor_sync(0xffffffffu, th, 1));
                th = fmaxf(th, __shfl_xor_sync(0xffffffffu, th, 2));
                tmax[i][0] = tl; tmax[i][1] = th;
                if (q4 == 0) {
                    smax[wc * 128 + wr * 32 + 16 * i + rl]     = tl;
                    smax[wc * 128 + wr * 32 + 16 * i + rl + 8] = th;
                }
            }
        }
        __syncthreads();       // B2: K_t consumed + partial maxes visible

        if (t + 1 < nkt) {
            flash_load_k(sb, kbh + (size_t)(t + 1) * FBN * DHd,
                         kbl + (size_t)(t + 1) * FBN * DHd);
            CP_COMMIT();
        }

        float aexp[2][2], psum[2][2];
        if (active) {
            // combine max across the warp pair; exponentiate; store P; partial sums
#pragma unroll
            for (int i = 0; i < 2; i++) {
#pragma unroll
                for (int hf = 0; hf < 2; hf++) {
                    const int rw = wr * 32 + 16 * i + rl + 8 * hf;
                    const float om = smax[(wc ^ 1) * 128 + rw];
                    const float mn = fmaxf(mst[i][hf], fmaxf(tmax[i][hf], om));
                    aexp[i][hf] = __expf(mst[i][hf] - mn);
                    mst[i][hf] = mn;
                }
                float s0 = 0.f, s1 = 0.f;
                uint32_t* ph = Ph32 + (wr * 32 + 16 * i + rl) * 36;
                uint32_t* pl = Pl32 + (wr * 32 + 16 * i + rl) * 36;
#pragma unroll
                for (int j = 0; j < 4; j++) {
                    float p0 = __expf(sacc[i][j][0] - mst[i][0]);
                    float p1 = __expf(sacc[i][j][1] - mst[i][0]);
                    float p2 = __expf(sacc[i][j][2] - mst[i][1]);
                    float p3 = __expf(sacc[i][j][3] - mst[i][1]);
                    s0 += p0 + p1;
                    s1 += p2 + p3;
                    uint32_t hh, ll;
                    bf16_split2(p0, p1, hh, ll);
                    ph[wc * 16 + j * 4 + q4] = hh;
                    pl[wc * 16 + j * 4 + q4] = ll;
                    bf16_split2(p2, p3, hh, ll);
                    ph[8 * 36 + wc * 16 + j * 4 + q4] = hh;
                    pl[8 * 36 + wc * 16 + j * 4 + q4] = ll;
                }
                s0 += __shfl_xor_sync(0xffffffffu, s0, 1);
                s0 += __shfl_xor_sync(0xffffffffu, s0, 2);
                s1 += __shfl_xor_sync(0xffffffffu, s1, 1);
                s1 += __shfl_xor_sync(0xffffffffu, s1, 2);
                psum[i][0] = s0; psum[i][1] = s1;
                if (q4 == 0) {
                    ssum[wc * 128 + wr * 32 + 16 * i + rl]     = s0;
                    ssum[wc * 128 + wr * 32 + 16 * i + rl + 8] = s1;
                }
            }
        }
        __syncthreads();       // B3: full P + partial sums visible

        if (active) {
#pragma unroll
            for (int i = 0; i < 2; i++)
#pragma unroll
                for (int hf = 0; hf < 2; hf++) {
                    const int rw = wr * 32 + 16 * i + rl + 8 * hf;
                    lst[i][hf] = lst[i][hf] * aexp[i][hf] + psum[i][hf]
                               + ssum[(wc ^ 1) * 128 + rw];
                }
#pragma unroll
            for (int i = 0; i < 2; i++)
#pragma unroll
                for (int nt = 0; nt < 8; nt++) {
                    o[i][nt][0] *= aexp[i][0]; o[i][nt][1] *= aexp[i][0];
                    o[i][nt][2] *= aexp[i][1]; o[i][nt][3] *= aexp[i][1];
                }
            __syncwarp();

            // O += P @ V  (P rows own 32, all 64 k; V d-cols = this wc's half)
            const uint32_t vAddr = sb + F_V0H + (uint32_t)(t & 1) * F_VSTR + vAddrOff;
#pragma unroll
            for (int ks = 0; ks < 4; ks++) {
                uint32_t p0h[4], p0l[4], p1h[4], p1l[4];
                ldsm_x4(p0h, pAddr + (uint32_t)(ks * 32));
                ldsm_x4(p0l, pAddr + (F_PL - F_PH) + (uint32_t)(ks * 32));
                ldsm_x4(p1h, pAddr + (uint32_t)(16 * 144 + ks * 32));
                ldsm_x4(p1l, pAddr + (F_PL - F_PH) + (uint32_t)(16 * 144 + ks * 32));
#pragma unroll
                for (int ntp = 0; ntp < 4; ntp++) {
                    uint32_t vh4[4], vl4[4];
                    ldsm_x4(vh4, vAddr + (uint32_t)(ntp * 16 * 144 + ks * 32));
                    ldsm_x4(vl4, vAddr + F_VLO + (uint32_t)(ntp * 16 * 144 + ks * 32));
                    mma_bf16(o[0][2 * ntp], p0h, vh4[0], vh4[1]);
                    mma_bf16(o[0][2 * ntp], p0l, vh4[0], vh4[1]);
                    mma_bf16(o[0][2 * ntp], p0h, vl4[0], vl4[1]);
                    mma_bf16(o[0][2 * ntp + 1], p0h, vh4[2], vh4[3]);
                    mma_bf16(o[0][2 * ntp + 1], p0l, vh4[2], vh4[3]);
                    mma_bf16(o[0][2 * ntp + 1], p0h, vl4[2], vl4[3]);
                    mma_bf16(o[1][2 * ntp], p1h, vh4[0], vh4[1]);
                    mma_bf16(o[1][2 * ntp], p1l, vh4[0], vh4[1]);
                    mma_bf16(o[1][2 * ntp], p1h, vl4[0], vl4[1]);
                    mma_bf16(o[1][2 * ntp + 1], p1h, vh4[2], vh4[3]);
                    mma_bf16(o[1][2 * ntp + 1], p1l, vh4[2], vh4[3]);
                    mma_bf16(o[1][2 * ntp + 1], p1h, vl4[2], vl4[3]);
                }
            }
        }
        // V_t reads protected by next iteration's B1 (prefetch targets other buffer)
    }

    // Epilogue: divide by l, split, write att hi/lo [B,T,D]
    __nv_bfloat16* oh = g_atth + ((size_t)(b * Tt + rowb)) * Dd + h * DHd;
    __nv_bfloat16* ol = g_attl + ((size_t)(b * Tt + rowb)) * Dd + h * DHd;
#pragma unroll
    for (int i = 0; i < 2; i++) {
        const float il0 = 1.f / lst[i][0];
        const float il1 = 1.f / lst[i][1];
#pragma unroll
        for (int nt = 0; nt < 8; nt++) {
            uint32_t hh, ll;
            size_t idx0 = (size_t)(16 * i + rl) * Dd + wc * 64 + nt * 8 + 2 * q4;
            bf16_split2(o[i][nt][0] * il0, o[i][nt][1] * il0, hh, ll);
            *(uint32_t*)(oh + idx0) = hh;
            *(uint32_t*)(ol + idx0) = ll;
            size_t idx1 = (size_t)(16 * i + rl + 8) * Dd + wc * 64 + nt * 8 + 2 * q4;
            bf16_split2(o[i][nt][2] * il1, o[i][nt][3] * il1, hh, ll);
            *(uint32_t*)(oh + idx1) = hh;
            *(uint32_t*)(ol + idx1) = ll;
        }
    }
}

// ===========================================================================
extern "C" void kernel_launch(void* const* d_in, const int* in_sizes, int n_in,
                              void* d_out, int out_size)
{
    const float* x  = (const float*)d_in[0];
    const float* Wq = (const float*)d_in[1];
    const float* bq = (const float*)d_in[2];
    const float* Wk = (const float*)d_in[3];
    const float* bk = (const float*)d_in[4];
    const float* Wv = (const float*)d_in[5];
    const float* bv = (const float*)d_in[6];
    const float* Wo = (const float*)d_in[7];
    const float* bo = (const float*)d_in[8];
    float* out = (float*)d_out;

    __nv_bfloat16 *xh, *xl, *wth, *wtl, *atth, *attl;
    cudaGetSymbolAddress((void**)&xh,   g_xh);
    cudaGetSymbolAddress((void**)&xl,   g_xl);
    cudaGetSymbolAddress((void**)&wth,  g_wth);
    cudaGetSymbolAddress((void**)&wtl,  g_wtl);
    cudaGetSymbolAddress((void**)&atth, g_atth);
    cudaGetSymbolAddress((void**)&attl, g_attl);

    // 1) Convert inputs to bf16 hi/lo (x natural, all 4 W transposed, fused)
    conv_x_kernel<<<(Mm * Dd) / 1024, 256>>>(x, xh, xl);
    dim3 wgrid(Dd / 32, Dd / 32, 4);
    conv_w_all<<<wgrid, dim3(32, 8)>>>(Wq, Wk, Wv, Wo, wth, wtl);

    cudaFuncSetAttribute(gemm_qkv, cudaFuncAttributeMaxDynamicSharedMemorySize, GEMM_SMEM);
    cudaFuncSetAttribute(gemm_out, cudaFuncAttributeMaxDynamicSharedMemorySize, GEMM_SMEM);

    // 2) Fused QKV projections (one launch, one tail)
    dim3 qkvgrid(Dd / GBN, Mm / GBM, 3);   // (16, 64, 3)
    gemm_qkv<<<qkvgrid, 256, GEMM_SMEM>>>(xh, xl, wth, wtl, bq, bk, bv);

    // 3) Flash attention
    cudaFuncSetAttribute(flash_tc, cudaFuncAttributeMaxDynamicSharedMemorySize, FLASH_SMEM);
    dim3 fgrid(Tt / FBM, Hh, Bq);          // (16, 16, 4)
    flash_tc<<<fgrid, 256, FLASH_SMEM>>>();

    // 4) Output projection (fp32 out)
    dim3 ogrid(Dd / GBN, Mm / GBM);        // (16, 64)
    gemm_out<<<ogrid, 256, GEMM_SMEM>>>(atth, attl, wth + 3 * (size_t)Dd * Dd,
                                        wtl + 3 * (size_t)Dd * Dd, bo, out);
}

// round 16
// speedup vs baseline: 1.0851x; 1.0258x over previous
#include <cuda_runtime.h>
#include <cuda_bf16.h>
#include <math_constants.h>
#include <cstdint>

#define Bq  4
#define Tt  2048
#define Dd  2048
#define Hh  16
#define DHd 128
#define Mm  (Bq * Tt)        // 8192
#define SCALE 0.08838834764831845f  // DH^-0.5

// ---------------------------------------------------------------------------
// Persistent bf16 hi/lo tensors (allocation-free rule: __device__ globals)
// ---------------------------------------------------------------------------
__device__ __align__(256) __nv_bfloat16 g_xh[Mm * Dd];
__device__ __align__(256) __nv_bfloat16 g_xl[Mm * Dd];
__device__ __align__(256) __nv_bfloat16 g_wth[4][Dd * Dd];   // W^T hi, [N][K]
__device__ __align__(256) __nv_bfloat16 g_wtl[4][Dd * Dd];   // W^T lo
__device__ __align__(256) __nv_bfloat16 g_qh[Bq * Hh * Tt * DHd];
__device__ __align__(256) __nv_bfloat16 g_ql[Bq * Hh * Tt * DHd];
__device__ __align__(256) __nv_bfloat16 g_kh[Bq * Hh * Tt * DHd];
__device__ __align__(256) __nv_bfloat16 g_kl[Bq * Hh * Tt * DHd];
__device__ __align__(256) __nv_bfloat16 g_vth[Bq * Hh * DHd * Tt];  // [b,h,d,t]
__device__ __align__(256) __nv_bfloat16 g_vtl[Bq * Hh * DHd * Tt];
__device__ __align__(256) __nv_bfloat16 g_atth[Bq * Tt * Dd];
__device__ __align__(256) __nv_bfloat16 g_attl[Bq * Tt * Dd];

// ===========================================================================
// Helpers
// ===========================================================================
__device__ __forceinline__ uint32_t smem_u32(const void* p) {
    uint32_t a;
    asm("{ .reg .u64 t; cvta.to.shared.u64 t, %1; cvt.u32.u64 %0, t; }" : "=r"(a) : "l"(p));
    return a;
}
__device__ __forceinline__ void cp16(uint32_t dst, const void* src) {
    asm volatile("cp.async.cg.shared.global [%0], [%1], 16;" :: "r"(dst), "l"(src));
}
#define CP_COMMIT() asm volatile("cp.async.commit_group;" ::: "memory")
#define CP_WAIT0()  asm volatile("cp.async.wait_group 0;" ::: "memory")
#define CP_WAIT1()  asm volatile("cp.async.wait_group 1;" ::: "memory")

__device__ __forceinline__ void mma_bf16(float* c, const uint32_t* a,
                                         uint32_t b0, uint32_t b1) {
    asm volatile(
        "mma.sync.aligned.m16n8k16.row.col.f32.bf16.bf16.f32 "
        "{%0,%1,%2,%3}, {%4,%5,%6,%7}, {%8,%9}, {%0,%1,%2,%3};"
        : "+f"(c[0]), "+f"(c[1]), "+f"(c[2]), "+f"(c[3])
        : "r"(a[0]), "r"(a[1]), "r"(a[2]), "r"(a[3]), "r"(b0), "r"(b1));
}
__device__ __forceinline__ void ldsm_x4(uint32_t* r, uint32_t addr) {
    asm volatile("ldmatrix.sync.aligned.m8n8.x4.shared.b16 {%0,%1,%2,%3}, [%4];"
        : "=r"(r[0]), "=r"(r[1]), "=r"(r[2]), "=r"(r[3]) : "r"(addr));
}
__device__ __forceinline__ uint32_t pack_bf16(float v0, float v1) {
    uint32_t h;
    asm("cvt.rn.bf16x2.f32 %0, %1, %2;" : "=r"(h) : "f"(v1), "f"(v0));
    return h;
}
// Split pair of fp32 into bf16x2 hi + bf16x2 residual (lower 16 bits = v0)
__device__ __forceinline__ void bf16_split2(float v0, float v1,
                                            uint32_t& hi, uint32_t& lo) {
    uint32_t h = pack_bf16(v0, v1);
    float f0 = __uint_as_float(h << 16);
    float f1 = __uint_as_float(h & 0xffff0000u);
    lo = pack_bf16(v0 - f0, v1 - f1);
    hi = h;
}

// ===========================================================================
// Conversion kernels
// ===========================================================================
__global__ __launch_bounds__(256)
void conv_x_kernel(const float* __restrict__ src,
                   __nv_bfloat16* __restrict__ hi, __nv_bfloat16* __restrict__ lo)
{
    const size_t i4 = ((size_t)blockIdx.x * 256 + threadIdx.x) * 4;
    float4 v = *(const float4*)(src + i4);
    uint32_t h0, l0, h1, l1;
    bf16_split2(v.x, v.y, h0, l0);
    bf16_split2(v.z, v.w, h1, l1);
    *(uint2*)(hi + i4) = make_uint2(h0, h1);
    *(uint2*)(lo + i4) = make_uint2(l0, l1);
}

// Transpose all 4 W [K][N] -> W^T [N][K], split to bf16 hi/lo. gridDim.z = 4.
__global__ __launch_bounds__(256)
void conv_w_all(const float* __restrict__ W0, const float* __restrict__ W1,
                const float* __restrict__ W2, const float* __restrict__ W3,
                __nv_bfloat16* __restrict__ Th, __nv_bfloat16* __restrict__ Tl)
{
    const int z = blockIdx.z;
    const float* W = (z == 0) ? W0 : (z == 1) ? W1 : (z == 2) ? W2 : W3;
    __nv_bfloat16* th = Th + (size_t)z * Dd * Dd;
    __nv_bfloat16* tl = Tl + (size_t)z * Dd * Dd;

    __shared__ float tile[32][33];
    int x = blockIdx.x * 32 + threadIdx.x;
    int y = blockIdx.y * 32 + threadIdx.y;
#pragma unroll
    for (int j = 0; j < 32; j += 8)
        tile[threadIdx.y + j][threadIdx.x] = W[(size_t)(y + j) * Dd + x];
    __syncthreads();
    int n = blockIdx.x * 32 + threadIdx.y;
    int k = blockIdx.y * 32 + threadIdx.x;
#pragma unroll
    for (int j = 0; j < 32; j += 8) {
        float v = tile[threadIdx.x][threadIdx.y + j];
        __nv_bfloat16 h = __float2bfloat16(v);
        __nv_bfloat16 l = __float2bfloat16(v - __bfloat162float(h));
        th[(size_t)(n + j) * Dd + k] = h;
        tl[(size_t)(n + j) * Dd + k] = l;
    }
}

// ===========================================================================
// bf16 hi/lo tensor-core GEMM core (R11/R15 config: best measured).
// BM=BN=128, BK=32, 256 threads (8 warps 2x4), warp tile 64x32.
// 3-stage cp.async ring (96KB) at 2 CTAs/SM. Dense 64B rows + XOR swizzle.
// ===========================================================================
#define GBM 128
#define GBN 128
#define GBK 32
#define TILEB 8192                    // 128 rows * 64B
#define STAGEB (4 * TILEB)            // 32768: Ah|Al|Bh|Bl
#define GEMM_SMEM (3 * STAGEB)        // 98304 -> 2 CTAs/SM

__device__ __forceinline__ void load_stage(uint32_t sdst,
        const __nv_bfloat16* __restrict__ Ah, const __nv_bfloat16* __restrict__ Al,
        const __nv_bfloat16* __restrict__ Bh, const __nv_bfloat16* __restrict__ Bl,
        int m0, int n0, int k0)
{
    const int tid = threadIdx.x;
#pragma unroll
    for (int l = 0; l < 2; l++) {
        int e = tid + 256 * l;
        int r = e >> 2, c = e & 3;
        int cp_ = c ^ ((r >> 1) & 3);
        uint32_t doff = (uint32_t)(r * 64 + cp_ * 16);
        size_t soff = (size_t)(m0 + r) * Dd + k0 + c * 8;
        cp16(sdst + doff, Ah + soff);
        cp16(sdst + TILEB + doff, Al + soff);
    }
#pragma unroll
    for (int l = 0; l < 2; l++) {
        int e = tid + 256 * l;
        int r = e >> 2, c = e & 3;
        int cp_ = c ^ ((r >> 1) & 3);
        uint32_t doff = (uint32_t)(r * 64 + cp_ * 16);
        size_t soff = (size_t)(n0 + r) * Dd + k0 + c * 8;
        cp16(sdst + 2 * TILEB + doff, Bh + soff);
        cp16(sdst + 3 * TILEB + doff, Bl + soff);
    }
}

__device__ __forceinline__ void gemm_mainloop(
        uint32_t sbase,
        const __nv_bfloat16* __restrict__ Ah, const __nv_bfloat16* __restrict__ Al,
        const __nv_bfloat16* __restrict__ Bth, const __nv_bfloat16* __restrict__ Btl,
        int m0, int n0, float acc[4][4][4])
{
    const int lane = threadIdx.x & 31;
    const int wid  = threadIdx.x >> 5;
    const int wm = wid >> 2, wn = wid & 3;
    const int lr = lane & 7, g = lane >> 3;
    const int swz = (lr >> 1) & 3;
    const uint32_t arow = (uint32_t)((wm * 64 + (g & 1) * 8 + lr) * 64);
    const int akh = g >> 1;
    const uint32_t brow = (uint32_t)((wn * 32 + (g >> 1) * 8 + lr) * 64);
    const int bkh = g & 1;

    load_stage(sbase, Ah, Al, Bth, Btl, m0, n0, 0);
    CP_COMMIT();
    load_stage(sbase + STAGEB, Ah, Al, Bth, Btl, m0, n0, GBK);
    CP_COMMIT();

    const int NITER = Dd / GBK;   // 64
    int cur = 0;
    for (int it = 0; it < NITER; it++) {
        if (it == NITER - 1) { CP_WAIT0(); } else { CP_WAIT1(); }
        __syncthreads();
        const uint32_t Sb = sbase + (uint32_t)cur * STAGEB;
        if (it + 2 < NITER) {
            int pf = cur + 2; if (pf >= 3) pf -= 3;
            load_stage(sbase + (uint32_t)pf * STAGEB, Ah, Al, Bth, Btl,
                       m0, n0, (it + 2) * GBK);
            CP_COMMIT();
        }
#pragma unroll
        for (int ks = 0; ks < 2; ks++) {
            const uint32_t ca = (uint32_t)(((ks * 2 + akh) ^ swz) * 16);
            const uint32_t cb = (uint32_t)(((ks * 2 + bkh) ^ swz) * 16);
            uint32_t ah[4][4], al[4][4];
#pragma unroll
            for (int i = 0; i < 4; i++) {
                ldsm_x4(ah[i], Sb + arow + (uint32_t)(i * 1024) + ca);
                ldsm_x4(al[i], Sb + TILEB + arow + (uint32_t)(i * 1024) + ca);
            }
#pragma unroll
            for (int jj = 0; jj < 2; jj++) {
                uint32_t bh4[4], bl4[4];
                ldsm_x4(bh4, Sb + 2 * TILEB + brow + (uint32_t)(jj * 1024) + cb);
                ldsm_x4(bl4, Sb + 3 * TILEB + brow + (uint32_t)(jj * 1024) + cb);
#pragma unroll
                for (int i = 0; i < 4; i++) {
                    mma_bf16(acc[i][2 * jj], ah[i], bh4[0], bh4[1]);
                    mma_bf16(acc[i][2 * jj], al[i], bh4[0], bh4[1]);
                    mma_bf16(acc[i][2 * jj], ah[i], bl4[0], bl4[1]);
                    mma_bf16(acc[i][2 * jj + 1], ah[i], bh4[2], bh4[3]);
                    mma_bf16(acc[i][2 * jj + 1], al[i], bh4[2], bh4[3]);
                    mma_bf16(acc[i][2 * jj + 1], ah[i], bl4[2], bl4[3]);
                }
            }
        }
        cur++; if (cur >= 3) cur = 0;
    }
}

// Fused QKV projection: gridDim.z selects q/k/v weight + epilogue.
__global__ __launch_bounds__(256, 2)
void gemm_qkv(const __nv_bfloat16* __restrict__ xh, const __nv_bfloat16* __restrict__ xl,
              const __nv_bfloat16* __restrict__ wth, const __nv_bfloat16* __restrict__ wtl,
              const float* __restrict__ bq, const float* __restrict__ bk,
              const float* __restrict__ bv)
{
    extern __shared__ char smem[];
    const uint32_t sbase = smem_u32(smem);
    const int z = blockIdx.z;
    const __nv_bfloat16* Bth = wth + (size_t)z * Dd * Dd;
    const __nv_bfloat16* Btl = wtl + (size_t)z * Dd * Dd;
    const float* bias = (z == 0) ? bq : (z == 1) ? bk : bv;
    const int m0 = blockIdx.y * GBM;
    const int n0 = blockIdx.x * GBN;

    float acc[4][4][4];
#pragma unroll
    for (int i = 0; i < 4; i++)
#pragma unroll
        for (int j = 0; j < 4; j++)
#pragma unroll
            for (int r = 0; r < 4; r++) acc[i][j][r] = 0.f;

    gemm_mainloop(sbase, xh, xl, Bth, Btl, m0, n0, acc);

    const int lane = threadIdx.x & 31;
    const int wid  = threadIdx.x >> 5;
    const int q4 = lane & 3, g8 = lane >> 2;
    const int wm = wid >> 2, wn = wid & 3;
    const int mbase = m0 + wm * 64;
#pragma unroll
    for (int j = 0; j < 4; j++) {
        const int nc = wn * 32 + j * 8 + 2 * q4;
        const float bx = bias[n0 + nc];
        const float by = bias[n0 + nc + 1];
#pragma unroll
        for (int i = 0; i < 4; i++) {
#pragma unroll
            for (int half = 0; half < 2; half++) {
                const int m = mbase + i * 16 + g8 + half * 8;
                float vx = acc[i][j][half * 2]     + bx;
                float vy = acc[i][j][half * 2 + 1] + by;
                const int h = n0 >> 7;
                const int b = m >> 11;
                const int t = m & 2047;
                if (z == 2) {
                    size_t base = ((size_t)(b * Hh + h) * DHd + nc) * Tt + t;
                    __nv_bfloat16 h0 = __float2bfloat16(vx);
                    __nv_bfloat16 h1 = __float2bfloat16(vy);
                    g_vth[base]       = h0;
                    g_vth[base + Tt]  = h1;
                    g_vtl[base]       = __float2bfloat16(vx - __bfloat162float(h0));
                    g_vtl[base + Tt]  = __float2bfloat16(vy - __bfloat162float(h1));
                } else {
                    __nv_bfloat16* dh = (z == 0) ? g_qh : g_kh;
                    __nv_bfloat16* dl = (z == 0) ? g_ql : g_kl;
                    size_t base = ((size_t)((b * Hh + h) * Tt) + t) * DHd + nc;
                    uint32_t hh, ll;
                    bf16_split2(vx, vy, hh, ll);
                    *(uint32_t*)(dh + base) = hh;
                    *(uint32_t*)(dl + base) = ll;
                }
            }
        }
    }
}

// Output projection: fp32 row-major result.
__global__ __launch_bounds__(256, 2)
void gemm_out(const __nv_bfloat16* __restrict__ Ah, const __nv_bfloat16* __restrict__ Al,
              const __nv_bfloat16* __restrict__ Bth, const __nv_bfloat16* __restrict__ Btl,
              const float* __restrict__ bias, float* __restrict__ Cout)
{
    extern __shared__ char smem[];
    const uint32_t sbase = smem_u32(smem);
    const int m0 = blockIdx.y * GBM;
    const int n0 = blockIdx.x * GBN;

    float acc[4][4][4];
#pragma unroll
    for (int i = 0; i < 4; i++)
#pragma unroll
        for (int j = 0; j < 4; j++)
#pragma unroll
            for (int r = 0; r < 4; r++) acc[i][j][r] = 0.f;

    gemm_mainloop(sbase, Ah, Al, Bth, Btl, m0, n0, acc);

    const int lane = threadIdx.x & 31;
    const int wid  = threadIdx.x >> 5;
    const int q4 = lane & 3, g8 = lane >> 2;
    const int wm = wid >> 2, wn = wid & 3;
    const int mbase = m0 + wm * 64;
#pragma unroll
    for (int j = 0; j < 4; j++) {
        const int nc = wn * 32 + j * 8 + 2 * q4;
        const float bx = bias[n0 + nc];
        const float by = bias[n0 + nc + 1];
#pragma unroll
        for (int i = 0; i < 4; i++) {
#pragma unroll
            for (int half = 0; half < 2; half++) {
                const int m = mbase + i * 16 + g8 + half * 8;
                *(float2*)(Cout + (size_t)m * Dd + n0 + nc) =
                    make_float2(acc[i][j][half * 2] + bx, acc[i][j][half * 2 + 1] + by);
            }
        }
    }
}

// ===========================================================================
// Flash attention (causal), bf16 hi/lo, 3-pass MMA, warp-local online softmax.
// BM=128 (8 warps x 16 rows), BN=64, DH=128, 256 threads, 1 CTA/SM.
// K AND V double-buffered; ONE __syncthreads per iteration -> warps skew so
// one warp's softmax overlaps another's MMAs.
// Dense rows (Q/K 256B, V/P 128B) with 8-row XOR chunk swizzle (c ^= r&7).
// ===========================================================================
#define FBM 128
#define FBN 64
#define F_QH   0u          // 128x256B = 32768
#define F_QL   32768u
#define F_K0   65536u      // per buffer: hi 16384 | lo 16384; stride 32768
#define F_KLO  16384u
#define F_KSTR 32768u
#define F_V0   131072u     // per buffer: hi 16384 | lo 16384; stride 32768
#define F_VLO  16384u
#define F_VSTR 32768u
#define F_PH   196608u     // 128x128B hi + lo
#define F_PL   212992u
#define FLASH_SMEM 229376  // 224 KB

__device__ __forceinline__ void flash_load_q(uint32_t sb,
        const __nv_bfloat16* __restrict__ qh, const __nv_bfloat16* __restrict__ ql) {
    const int tid = threadIdx.x;
#pragma unroll
    for (int l = 0; l < 8; l++) {
        int e = tid + l * 256;
        int r = e >> 4, c = e & 15;
        int cp_ = c ^ (r & 7);
        uint32_t doff = (uint32_t)(r * 256 + cp_ * 16);
        cp16(sb + F_QH + doff, qh + r * 128 + c * 8);
        cp16(sb + F_QL + doff, ql + r * 128 + c * 8);
    }
}
__device__ __forceinline__ void flash_load_k(uint32_t dst,
        const __nv_bfloat16* __restrict__ kh, const __nv_bfloat16* __restrict__ kl) {
    const int tid = threadIdx.x;
#pragma unroll
    for (int l = 0; l < 4; l++) {
        int e = tid + l * 256;
        int r = e >> 4, c = e & 15;
        int cp_ = c ^ (r & 7);
        uint32_t doff = (uint32_t)(r * 256 + cp_ * 16);
        cp16(dst + doff, kh + r * 128 + c * 8);
        cp16(dst + F_KLO + doff, kl + r * 128 + c * 8);
    }
}
__device__ __forceinline__ void flash_load_v(uint32_t dst,
        const __nv_bfloat16* __restrict__ vh, const __nv_bfloat16* __restrict__ vl) {
    const int tid = threadIdx.x;
#pragma unroll
    for (int l = 0; l < 4; l++) {
        int e = tid + l * 256;
        int r = e >> 3, c = e & 7;
        int cp_ = c ^ (r & 7);
        uint32_t doff = (uint32_t)(r * 128 + cp_ * 16);
        cp16(dst + doff, vh + (size_t)r * Tt + c * 8);
        cp16(dst + F_VLO + doff, vl + (size_t)r * Tt + c * 8);
    }
}

__global__ __launch_bounds__(256, 1)
void flash_tc()
{
    extern __shared__ char smc[];
    const uint32_t sb = smem_u32(smc);
    const int qb = (gridDim.x - 1) - blockIdx.x;    // longest-job-first
    const int h  = blockIdx.y;
    const int b  = blockIdx.z;
    const int q0 = qb * FBM;
    const int tid  = threadIdx.x;
    const int w    = tid >> 5;
    const int lane = tid & 31;
    const int q4   = lane & 3;
    const int rl   = lane >> 2;
    const int lr   = lane & 7;
    const int g    = lane >> 3;

    uint32_t* Ph32 = (uint32_t*)(smc + F_PH);
    uint32_t* Pl32 = (uint32_t*)(smc + F_PL);

    // ldmatrix row-base addresses (chunk xor applied per-ks at use site)
    const uint32_t qRow = sb + F_QH + (uint32_t)((w * 16 + (g & 1) * 8 + lr) * 256);
    const uint32_t kRowOff = (uint32_t)(((g >> 1) * 8 + lr) * 256);   // + jj*4096, rel to kbuf
    const uint32_t pRow = sb + F_PH + (uint32_t)((w * 16 + (g & 1) * 8 + lr) * 128);
    const uint32_t vRowOff = (uint32_t)(((g >> 1) * 8 + lr) * 128);   // + ntp*2048, rel to vbuf
    const int aKH = g >> 1;    // A-side chunk half (Q, P)
    const int bKH = g & 1;     // B-side chunk half (K, V)

    const size_t bh = (size_t)(b * Hh + h) * Tt;
    const __nv_bfloat16* kbh = g_kh + bh * DHd;
    const __nv_bfloat16* kbl = g_kl + bh * DHd;
    const __nv_bfloat16* vbh = g_vth + (size_t)(b * Hh + h) * DHd * Tt;
    const __nv_bfloat16* vbl = g_vtl + (size_t)(b * Hh + h) * DHd * Tt;

    flash_load_q(sb, g_qh + (bh + q0) * DHd, g_ql + (bh + q0) * DHd);
    flash_load_k(sb + F_K0, kbh, kbl);
    flash_load_v(sb + F_V0, vbh, vbl);
    CP_COMMIT();

    float m_lo = -1e30f, m_hi = -1e30f, l_lo = 0.f, l_hi = 0.f;
    float o[16][4];
#pragma unroll
    for (int nt = 0; nt < 16; nt++)
#pragma unroll
        for (int r = 0; r < 4; r++) o[nt][r] = 0.f;

    const int rowbase = q0 + w * 16;
    const int nkt = 2 * qb + 2;

    for (int t = 0; t < nkt; t++) {
        const int k0 = t * FBN;
        const bool active = (k0 <= rowbase + 15);
        CP_WAIT0();            // K_t and V_t arrived
        __syncthreads();       // SINGLE barrier: protects buffer (t+1)&1 (read at t-1)

        if (t + 1 < nkt) {
            flash_load_k(sb + F_K0 + (uint32_t)((t + 1) & 1) * F_KSTR,
                         kbh + (size_t)(t + 1) * FBN * DHd,
                         kbl + (size_t)(t + 1) * FBN * DHd);
            flash_load_v(sb + F_V0 + (uint32_t)((t + 1) & 1) * F_VSTR,
                         vbh + (size_t)(t + 1) * FBN, vbl + (size_t)(t + 1) * FBN);
            CP_COMMIT();
        }

        if (active) {
            const uint32_t kbuf = sb + F_K0 + (uint32_t)(t & 1) * F_KSTR;
            float sacc[8][4];
#pragma unroll
            for (int j = 0; j < 8; j++)
#pragma unroll
                for (int r = 0; r < 4; r++) sacc[j][r] = 0.f;

#pragma unroll
            for (int ks = 0; ks < 8; ks++) {
                const uint32_t ca = (uint32_t)(((ks * 2 + aKH) ^ lr) * 16);
                const uint32_t cb = (uint32_t)(((ks * 2 + bKH) ^ lr) * 16);
                uint32_t ah[4], al[4];
                ldsm_x4(ah, qRow + ca);
                ldsm_x4(al, qRow + (F_QL - F_QH) + ca);
#pragma unroll
                for (int jj = 0; jj < 4; jj++) {
                    uint32_t bh4[4], bl4[4];
                    ldsm_x4(bh4, kbuf + kRowOff + (uint32_t)(jj * 4096) + cb);
                    ldsm_x4(bl4, kbuf + F_KLO + kRowOff + (uint32_t)(jj * 4096) + cb);
                    mma_bf16(sacc[2 * jj], ah, bh4[0], bh4[1]);
                    mma_bf16(sacc[2 * jj], al, bh4[0], bh4[1]);
                    mma_bf16(sacc[2 * jj], ah, bl4[0], bl4[1]);
                    mma_bf16(sacc[2 * jj + 1], ah, bh4[2], bh4[3]);
                    mma_bf16(sacc[2 * jj + 1], al, bh4[2], bh4[3]);
                    mma_bf16(sacc[2 * jj + 1], ah, bl4[2], bl4[3]);
                }
            }

            // Causal mask + warp-local online softmax
            const int R_lo = rowbase + rl;
            const int R_hi = R_lo + 8;
            const bool needmask = (k0 + FBN - 1) > rowbase;
            float tl = -1e30f, th = -1e30f;
#pragma unroll
            for (int j = 0; j < 8; j++) {
#pragma unroll
                for (int r = 0; r < 4; r++) sacc[j][r] *= SCALE;
                if (needmask) {
                    const int C = k0 + j * 8 + 2 * q4;
                    if (C > R_lo)     sacc[j][0] = -1e30f;
                    if (C + 1 > R_lo) sacc[j][1] = -1e30f;
                    if (C > R_hi)     sacc[j][2] = -1e30f;
                    if (C + 1 > R_hi) sacc[j][3] = -1e30f;
                }
                tl = fmaxf(tl, fmaxf(sacc[j][0], sacc[j][1]));
                th = fmaxf(th, fmaxf(sacc[j][2], sacc[j][3]));
            }
            tl = fmaxf(tl, __shfl_xor_sync(0xffffffffu, tl, 1));
            tl = fmaxf(tl, __shfl_xor_sync(0xffffffffu, tl, 2));
            th = fmaxf(th, __shfl_xor_sync(0xffffffffu, th, 1));
            th = fmaxf(th, __shfl_xor_sync(0xffffffffu, th, 2));

            const float mn_lo = fmaxf(m_lo, tl);
            const float mn_hi = fmaxf(m_hi, th);
            const float a_lo = __expf(m_lo - mn_lo);
            const float a_hi = __expf(m_hi - mn_hi);
            m_lo = mn_lo; m_hi = mn_hi;

            float sum_lo = 0.f, sum_hi = 0.f;
            uint32_t* prl_h = Ph32 + (w * 16 + rl) * 32;
            uint32_t* prl_l = Pl32 + (w * 16 + rl) * 32;
#pragma unroll
            for (int j = 0; j < 8; j++) {
                float p0 = __expf(sacc[j][0] - mn_lo);
                float p1 = __expf(sacc[j][1] - mn_lo);
                float p2 = __expf(sacc[j][2] - mn_hi);
                float p3 = __expf(sacc[j][3] - mn_hi);
                sum_lo += p0 + p1;
                sum_hi += p2 + p3;
                const int pidx = (j ^ rl) * 4 + q4;    // swizzled u32 index
                uint32_t hh, ll;
                bf16_split2(p0, p1, hh, ll);
                prl_h[pidx] = hh;
                prl_l[pidx] = ll;
                bf16_split2(p2, p3, hh, ll);
                prl_h[8 * 32 + pidx] = hh;
                prl_l[8 * 32 + pidx] = ll;
            }
            sum_lo += __shfl_xor_sync(0xffffffffu, sum_lo, 1);
            sum_lo += __shfl_xor_sync(0xffffffffu, sum_lo, 2);
            sum_hi += __shfl_xor_sync(0xffffffffu, sum_hi, 1);
            sum_hi += __shfl_xor_sync(0xffffffffu, sum_hi, 2);
            l_lo = l_lo * a_lo + sum_lo;
            l_hi = l_hi * a_hi + sum_hi;

#pragma unroll
            for (int nt = 0; nt < 16; nt++) {
                o[nt][0] *= a_lo; o[nt][1] *= a_lo;
                o[nt][2] *= a_hi; o[nt][3] *= a_hi;
            }
            __syncwarp();      // P rows warp-private: warp-level visibility sufficient

            // O += P @ V  (3-pass bf16)
            const uint32_t vbuf = sb + F_V0 + (uint32_t)(t & 1) * F_VSTR;
#pragma unroll
            for (int ks = 0; ks < 4; ks++) {
                const uint32_t ca = (uint32_t)(((ks * 2 + aKH) ^ lr) * 16);
                const uint32_t cb = (uint32_t)(((ks * 2 + bKH) ^ lr) * 16);
                uint32_t ph4[4], pl4[4];
                ldsm_x4(ph4, pRow + ca);
                ldsm_x4(pl4, pRow + (F_PL - F_PH) + ca);
#pragma unroll
                for (int ntp = 0; ntp < 8; ntp++) {
                    uint32_t vh4[4], vl4[4];
                    ldsm_x4(vh4, vbuf + vRowOff + (uint32_t)(ntp * 2048) + cb);
                    ldsm_x4(vl4, vbuf + F_VLO + vRowOff + (uint32_t)(ntp * 2048) + cb);
                    mma_bf16(o[2 * ntp], ph4, vh4[0], vh4[1]);
                    mma_bf16(o[2 * ntp], pl4, vh4[0], vh4[1]);
                    mma_bf16(o[2 * ntp], ph4, vl4[0], vl4[1]);
                    mma_bf16(o[2 * ntp + 1], ph4, vh4[2], vh4[3]);
                    mma_bf16(o[2 * ntp + 1], pl4, vh4[2], vh4[3]);
                    mma_bf16(o[2 * ntp + 1], ph4, vl4[2], vl4[3]);
                }
            }
        }
    }

    // Epilogue: divide by l, split, write att hi/lo [B,T,D]
    const float il_lo = 1.f / l_lo;
    const float il_hi = 1.f / l_hi;
    __nv_bfloat16* oh = g_atth + ((size_t)(b * Tt + rowbase)) * Dd + h * DHd;
    __nv_bfloat16* ol = g_attl + ((size_t)(b * Tt + rowbase)) * Dd + h * DHd;
#pragma unroll
    for (int nt = 0; nt < 16; nt++) {
        uint32_t hh, ll;
        size_t idx0 = (size_t)rl * Dd + nt * 8 + 2 * q4;
        bf16_split2(o[nt][0] * il_lo, o[nt][1] * il_lo, hh, ll);
        *(uint32_t*)(oh + idx0) = hh;
        *(uint32_t*)(ol + idx0) = ll;
        size_t idx1 = (size_t)(rl + 8) * Dd + nt * 8 + 2 * q4;
        bf16_split2(o[nt][2] * il_hi, o[nt][3] * il_hi, hh, ll);
        *(uint32_t*)(oh + idx1) = hh;
        *(uint32_t*)(ol + idx1) = ll;
    }
}

// ===========================================================================
extern "C" void kernel_launch(void* const* d_in, const int* in_sizes, int n_in,
                              void* d_out, int out_size)
{
    const float* x  = (const float*)d_in[0];
    const float* Wq = (const float*)d_in[1];
    const float* bq = (const float*)d_in[2];
    const float* Wk = (const float*)d_in[3];
    const float* bk = (const float*)d_in[4];
    const float* Wv = (const float*)d_in[5];
    const float* bv = (const float*)d_in[6];
    const float* Wo = (const float*)d_in[7];
    const float* bo = (const float*)d_in[8];
    float* out = (float*)d_out;

    __nv_bfloat16 *xh, *xl, *wth, *wtl, *atth, *attl;
    cudaGetSymbolAddress((void**)&xh,   g_xh);
    cudaGetSymbolAddress((void**)&xl,   g_xl);
    cudaGetSymbolAddress((void**)&wth,  g_wth);
    cudaGetSymbolAddress((void**)&wtl,  g_wtl);
    cudaGetSymbolAddress((void**)&atth, g_atth);
    cudaGetSymbolAddress((void**)&attl, g_attl);

    // 1) Convert inputs to bf16 hi/lo (x natural, all 4 W transposed, fused)
    conv_x_kernel<<<(Mm * Dd) / 1024, 256>>>(x, xh, xl);
    dim3 wgrid(Dd / 32, Dd / 32, 4);
    conv_w_all<<<wgrid, dim3(32, 8)>>>(Wq, Wk, Wv, Wo, wth, wtl);

    cudaFuncSetAttribute(gemm_qkv, cudaFuncAttributeMaxDynamicSharedMemorySize, GEMM_SMEM);
    cudaFuncSetAttribute(gemm_out, cudaFuncAttributeMaxDynamicSharedMemorySize, GEMM_SMEM);

    // 2) Fused QKV projections (one launch, one tail)
    dim3 qkvgrid(Dd / GBN, Mm / GBM, 3);   // (16, 64, 3)
    gemm_qkv<<<qkvgrid, 256, GEMM_SMEM>>>(xh, xl, wth, wtl, bq, bk, bv);

    // 3) Flash attention
    cudaFuncSetAttribute(flash_tc, cudaFuncAttributeMaxDynamicSharedMemorySize, FLASH_SMEM);
    dim3 fgrid(Tt / FBM, Hh, Bq);          // (16, 16, 4)
    flash_tc<<<fgrid, 256, FLASH_SMEM>>>();

    // 4) Output projection (fp32 out)
    dim3 ogrid(Dd / GBN, Mm / GBM);        // (16, 64)
    gemm_out<<<ogrid, 256, GEMM_SMEM>>>(atth, attl, wth + 3 * (size_t)Dd * Dd,
                                        wtl + 3 * (size_t)Dd * Dd, bo, out);
}

// round 17
// speedup vs baseline: 1.1051x; 1.0185x over previous
#include <cuda_runtime.h>
#include <cuda_bf16.h>
#include <math_constants.h>
#include <cstdint>

#define Bq  4
#define Tt  2048
#define Dd  2048
#define Hh  16
#define DHd 128
#define Mm  (Bq * Tt)        // 8192
#define SCALE 0.08838834764831845f  // DH^-0.5

// ---------------------------------------------------------------------------
// Persistent bf16 hi/lo tensors (allocation-free rule: __device__ globals)
// ---------------------------------------------------------------------------
__device__ __align__(256) __nv_bfloat16 g_xh[Mm * Dd];
__device__ __align__(256) __nv_bfloat16 g_xl[Mm * Dd];
__device__ __align__(256) __nv_bfloat16 g_wth[4][Dd * Dd];   // W^T hi, [N][K]
__device__ __align__(256) __nv_bfloat16 g_wtl[4][Dd * Dd];   // W^T lo
__device__ __align__(256) __nv_bfloat16 g_qh[Bq * Hh * Tt * DHd];
__device__ __align__(256) __nv_bfloat16 g_ql[Bq * Hh * Tt * DHd];
__device__ __align__(256) __nv_bfloat16 g_kh[Bq * Hh * Tt * DHd];
__device__ __align__(256) __nv_bfloat16 g_kl[Bq * Hh * Tt * DHd];
__device__ __align__(256) __nv_bfloat16 g_vth[Bq * Hh * DHd * Tt];  // [b,h,d,t]
__device__ __align__(256) __nv_bfloat16 g_vtl[Bq * Hh * DHd * Tt];
__device__ __align__(256) __nv_bfloat16 g_atth[Bq * Tt * Dd];
__device__ __align__(256) __nv_bfloat16 g_attl[Bq * Tt * Dd];

// ===========================================================================
// Helpers
// ===========================================================================
__device__ __forceinline__ uint32_t smem_u32(const void* p) {
    uint32_t a;
    asm("{ .reg .u64 t; cvta.to.shared.u64 t, %1; cvt.u32.u64 %0, t; }" : "=r"(a) : "l"(p));
    return a;
}
__device__ __forceinline__ void cp16(uint32_t dst, const void* src) {
    asm volatile("cp.async.cg.shared.global [%0], [%1], 16;" :: "r"(dst), "l"(src));
}
#define CP_COMMIT() asm volatile("cp.async.commit_group;" ::: "memory")
#define CP_WAIT0()  asm volatile("cp.async.wait_group 0;" ::: "memory")
#define CP_WAIT1()  asm volatile("cp.async.wait_group 1;" ::: "memory")

__device__ __forceinline__ void mma_bf16(float* c, const uint32_t* a,
                                         uint32_t b0, uint32_t b1) {
    asm volatile(
        "mma.sync.aligned.m16n8k16.row.col.f32.bf16.bf16.f32 "
        "{%0,%1,%2,%3}, {%4,%5,%6,%7}, {%8,%9}, {%0,%1,%2,%3};"
        : "+f"(c[0]), "+f"(c[1]), "+f"(c[2]), "+f"(c[3])
        : "r"(a[0]), "r"(a[1]), "r"(a[2]), "r"(a[3]), "r"(b0), "r"(b1));
}
__device__ __forceinline__ void ldsm_x4(uint32_t* r, uint32_t addr) {
    asm volatile("ldmatrix.sync.aligned.m8n8.x4.shared.b16 {%0,%1,%2,%3}, [%4];"
        : "=r"(r[0]), "=r"(r[1]), "=r"(r[2]), "=r"(r[3]) : "r"(addr));
}
__device__ __forceinline__ uint32_t pack_bf16(float v0, float v1) {
    uint32_t h;
    asm("cvt.rn.bf16x2.f32 %0, %1, %2;" : "=r"(h) : "f"(v1), "f"(v0));
    return h;
}
// Split pair of fp32 into bf16x2 hi + bf16x2 residual (lower 16 bits = v0)
__device__ __forceinline__ void bf16_split2(float v0, float v1,
                                            uint32_t& hi, uint32_t& lo) {
    uint32_t h = pack_bf16(v0, v1);
    float f0 = __uint_as_float(h << 16);
    float f1 = __uint_as_float(h & 0xffff0000u);
    lo = pack_bf16(v0 - f0, v1 - f1);
    hi = h;
}

// ===========================================================================
// Conversion kernels
// ===========================================================================
__global__ __launch_bounds__(256)
void conv_x_kernel(const float* __restrict__ src,
                   __nv_bfloat16* __restrict__ hi, __nv_bfloat16* __restrict__ lo)
{
    const size_t i4 = ((size_t)blockIdx.x * 256 + threadIdx.x) * 4;
    float4 v = *(const float4*)(src + i4);
    uint32_t h0, l0, h1, l1;
    bf16_split2(v.x, v.y, h0, l0);
    bf16_split2(v.z, v.w, h1, l1);
    *(uint2*)(hi + i4) = make_uint2(h0, h1);
    *(uint2*)(lo + i4) = make_uint2(l0, l1);
}

// Transpose all 4 W [K][N] -> W^T [N][K], split to bf16 hi/lo. gridDim.z = 4.
__global__ __launch_bounds__(256)
void conv_w_all(const float* __restrict__ W0, const float* __restrict__ W1,
                const float* __restrict__ W2, const float* __restrict__ W3,
                __nv_bfloat16* __restrict__ Th, __nv_bfloat16* __restrict__ Tl)
{
    const int z = blockIdx.z;
    const float* W = (z == 0) ? W0 : (z == 1) ? W1 : (z == 2) ? W2 : W3;
    __nv_bfloat16* th = Th + (size_t)z * Dd * Dd;
    __nv_bfloat16* tl = Tl + (size_t)z * Dd * Dd;

    __shared__ float tile[32][33];
    int x = blockIdx.x * 32 + threadIdx.x;
    int y = blockIdx.y * 32 + threadIdx.y;
#pragma unroll
    for (int j = 0; j < 32; j += 8)
        tile[threadIdx.y + j][threadIdx.x] = W[(size_t)(y + j) * Dd + x];
    __syncthreads();
    int n = blockIdx.x * 32 + threadIdx.y;
    int k = blockIdx.y * 32 + threadIdx.x;
#pragma unroll
    for (int j = 0; j < 32; j += 8) {
        float v = tile[threadIdx.x][threadIdx.y + j];
        __nv_bfloat16 h = __float2bfloat16(v);
        __nv_bfloat16 l = __float2bfloat16(v - __bfloat162float(h));
        th[(size_t)(n + j) * Dd + k] = h;
        tl[(size_t)(n + j) * Dd + k] = l;
    }
}

// ===========================================================================
// bf16 hi/lo tensor-core GEMM core (R11/R15 config: best measured).
// BM=BN=128, BK=32, 256 threads (8 warps 2x4), warp tile 64x32.
// 3-stage cp.async ring (96KB) at 2 CTAs/SM. Dense 64B rows + XOR swizzle.
// ===========================================================================
#define GBM 128
#define GBN 128
#define GBK 32
#define TILEB 8192                    // 128 rows * 64B
#define STAGEB (4 * TILEB)            // 32768: Ah|Al|Bh|Bl
#define GEMM_SMEM (3 * STAGEB)        // 98304 -> 2 CTAs/SM

__device__ __forceinline__ void load_stage(uint32_t sdst,
        const __nv_bfloat16* __restrict__ Ah, const __nv_bfloat16* __restrict__ Al,
        const __nv_bfloat16* __restrict__ Bh, const __nv_bfloat16* __restrict__ Bl,
        int m0, int n0, int k0)
{
    const int tid = threadIdx.x;
#pragma unroll
    for (int l = 0; l < 2; l++) {
        int e = tid + 256 * l;
        int r = e >> 2, c = e & 3;
        int cp_ = c ^ ((r >> 1) & 3);
        uint32_t doff = (uint32_t)(r * 64 + cp_ * 16);
        size_t soff = (size_t)(m0 + r) * Dd + k0 + c * 8;
        cp16(sdst + doff, Ah + soff);
        cp16(sdst + TILEB + doff, Al + soff);
    }
#pragma unroll
    for (int l = 0; l < 2; l++) {
        int e = tid + 256 * l;
        int r = e >> 2, c = e & 3;
        int cp_ = c ^ ((r >> 1) & 3);
        uint32_t doff = (uint32_t)(r * 64 + cp_ * 16);
        size_t soff = (size_t)(n0 + r) * Dd + k0 + c * 8;
        cp16(sdst + 2 * TILEB + doff, Bh + soff);
        cp16(sdst + 3 * TILEB + doff, Bl + soff);
    }
}

__device__ __forceinline__ void gemm_mainloop(
        uint32_t sbase,
        const __nv_bfloat16* __restrict__ Ah, const __nv_bfloat16* __restrict__ Al,
        const __nv_bfloat16* __restrict__ Bth, const __nv_bfloat16* __restrict__ Btl,
        int m0, int n0, float acc[4][4][4])
{
    const int lane = threadIdx.x & 31;
    const int wid  = threadIdx.x >> 5;
    const int wm = wid >> 2, wn = wid & 3;
    const int lr = lane & 7, g = lane >> 3;
    const int swz = (lr >> 1) & 3;
    const uint32_t arow = (uint32_t)((wm * 64 + (g & 1) * 8 + lr) * 64);
    const int akh = g >> 1;
    const uint32_t brow = (uint32_t)((wn * 32 + (g >> 1) * 8 + lr) * 64);
    const int bkh = g & 1;

    load_stage(sbase, Ah, Al, Bth, Btl, m0, n0, 0);
    CP_COMMIT();
    load_stage(sbase + STAGEB, Ah, Al, Bth, Btl, m0, n0, GBK);
    CP_COMMIT();

    const int NITER = Dd / GBK;   // 64
    int cur = 0;
    for (int it = 0; it < NITER; it++) {
        if (it == NITER - 1) { CP_WAIT0(); } else { CP_WAIT1(); }
        __syncthreads();
        const uint32_t Sb = sbase + (uint32_t)cur * STAGEB;
        if (it + 2 < NITER) {
            int pf = cur + 2; if (pf >= 3) pf -= 3;
            load_stage(sbase + (uint32_t)pf * STAGEB, Ah, Al, Bth, Btl,
                       m0, n0, (it + 2) * GBK);
            CP_COMMIT();
        }
#pragma unroll
        for (int ks = 0; ks < 2; ks++) {
            const uint32_t ca = (uint32_t)(((ks * 2 + akh) ^ swz) * 16);
            const uint32_t cb = (uint32_t)(((ks * 2 + bkh) ^ swz) * 16);
            uint32_t ah[4][4], al[4][4];
#pragma unroll
            for (int i = 0; i < 4; i++) {
                ldsm_x4(ah[i], Sb + arow + (uint32_t)(i * 1024) + ca);
                ldsm_x4(al[i], Sb + TILEB + arow + (uint32_t)(i * 1024) + ca);
            }
#pragma unroll
            for (int jj = 0; jj < 2; jj++) {
                uint32_t bh4[4], bl4[4];
                ldsm_x4(bh4, Sb + 2 * TILEB + brow + (uint32_t)(jj * 1024) + cb);
                ldsm_x4(bl4, Sb + 3 * TILEB + brow + (uint32_t)(jj * 1024) + cb);
#pragma unroll
                for (int i = 0; i < 4; i++) {
                    mma_bf16(acc[i][2 * jj], ah[i], bh4[0], bh4[1]);
                    mma_bf16(acc[i][2 * jj], al[i], bh4[0], bh4[1]);
                    mma_bf16(acc[i][2 * jj], ah[i], bl4[0], bl4[1]);
                    mma_bf16(acc[i][2 * jj + 1], ah[i], bh4[2], bh4[3]);
                    mma_bf16(acc[i][2 * jj + 1], al[i], bh4[2], bh4[3]);
                    mma_bf16(acc[i][2 * jj + 1], ah[i], bl4[2], bl4[3]);
                }
            }
        }
        cur++; if (cur >= 3) cur = 0;
    }
}

// Fused QKV projection: gridDim.z selects q/k/v weight + epilogue.
// q is pre-scaled by DH^-0.5 (folded out of the flash softmax path).
__global__ __launch_bounds__(256, 2)
void gemm_qkv(const __nv_bfloat16* __restrict__ xh, const __nv_bfloat16* __restrict__ xl,
              const __nv_bfloat16* __restrict__ wth, const __nv_bfloat16* __restrict__ wtl,
              const float* __restrict__ bq, const float* __restrict__ bk,
              const float* __restrict__ bv)
{
    extern __shared__ char smem[];
    const uint32_t sbase = smem_u32(smem);
    const int z = blockIdx.z;
    const __nv_bfloat16* Bth = wth + (size_t)z * Dd * Dd;
    const __nv_bfloat16* Btl = wtl + (size_t)z * Dd * Dd;
    const float* bias = (z == 0) ? bq : (z == 1) ? bk : bv;
    const int m0 = blockIdx.y * GBM;
    const int n0 = blockIdx.x * GBN;

    float acc[4][4][4];
#pragma unroll
    for (int i = 0; i < 4; i++)
#pragma unroll
        for (int j = 0; j < 4; j++)
#pragma unroll
            for (int r = 0; r < 4; r++) acc[i][j][r] = 0.f;

    gemm_mainloop(sbase, xh, xl, Bth, Btl, m0, n0, acc);

    const int lane = threadIdx.x & 31;
    const int wid  = threadIdx.x >> 5;
    const int q4 = lane & 3, g8 = lane >> 2;
    const int wm = wid >> 2, wn = wid & 3;
    const int mbase = m0 + wm * 64;
    const float oscale = (z == 0) ? SCALE : 1.0f;
#pragma unroll
    for (int j = 0; j < 4; j++) {
        const int nc = wn * 32 + j * 8 + 2 * q4;
        const float bx = bias[n0 + nc];
        const float by = bias[n0 + nc + 1];
#pragma unroll
        for (int i = 0; i < 4; i++) {
#pragma unroll
            for (int half = 0; half < 2; half++) {
                const int m = mbase + i * 16 + g8 + half * 8;
                float vx = (acc[i][j][half * 2]     + bx) * oscale;
                float vy = (acc[i][j][half * 2 + 1] + by) * oscale;
                const int h = n0 >> 7;
                const int b = m >> 11;
                const int t = m & 2047;
                if (z == 2) {
                    size_t base = ((size_t)(b * Hh + h) * DHd + nc) * Tt + t;
                    __nv_bfloat16 h0 = __float2bfloat16(vx);
                    __nv_bfloat16 h1 = __float2bfloat16(vy);
                    g_vth[base]       = h0;
                    g_vth[base + Tt]  = h1;
                    g_vtl[base]       = __float2bfloat16(vx - __bfloat162float(h0));
                    g_vtl[base + Tt]  = __float2bfloat16(vy - __bfloat162float(h1));
                } else {
                    __nv_bfloat16* dh = (z == 0) ? g_qh : g_kh;
                    __nv_bfloat16* dl = (z == 0) ? g_ql : g_kl;
                    size_t base = ((size_t)((b * Hh + h) * Tt) + t) * DHd + nc;
                    uint32_t hh, ll;
                    bf16_split2(vx, vy, hh, ll);
                    *(uint32_t*)(dh + base) = hh;
                    *(uint32_t*)(dl + base) = ll;
                }
            }
        }
    }
}

// Output projection: fp32 row-major result.
__global__ __launch_bounds__(256, 2)
void gemm_out(const __nv_bfloat16* __restrict__ Ah, const __nv_bfloat16* __restrict__ Al,
              const __nv_bfloat16* __restrict__ Bth, const __nv_bfloat16* __restrict__ Btl,
              const float* __restrict__ bias, float* __restrict__ Cout)
{
    extern __shared__ char smem[];
    const uint32_t sbase = smem_u32(smem);
    const int m0 = blockIdx.y * GBM;
    const int n0 = blockIdx.x * GBN;

    float acc[4][4][4];
#pragma unroll
    for (int i = 0; i < 4; i++)
#pragma unroll
        for (int j = 0; j < 4; j++)
#pragma unroll
            for (int r = 0; r < 4; r++) acc[i][j][r] = 0.f;

    gemm_mainloop(sbase, Ah, Al, Bth, Btl, m0, n0, acc);

    const int lane = threadIdx.x & 31;
    const int wid  = threadIdx.x >> 5;
    const int q4 = lane & 3, g8 = lane >> 2;
    const int wm = wid >> 2, wn = wid & 3;
    const int mbase = m0 + wm * 64;
#pragma unroll
    for (int j = 0; j < 4; j++) {
        const int nc = wn * 32 + j * 8 + 2 * q4;
        const float bx = bias[n0 + nc];
        const float by = bias[n0 + nc + 1];
#pragma unroll
        for (int i = 0; i < 4; i++) {
#pragma unroll
            for (int half = 0; half < 2; half++) {
                const int m = mbase + i * 16 + g8 + half * 8;
                *(float2*)(Cout + (size_t)m * Dd + n0 + nc) =
                    make_float2(acc[i][j][half * 2] + bx, acc[i][j][half * 2 + 1] + by);
            }
        }
    }
}

// ===========================================================================
// Flash attention (causal), bf16 hi/lo, 3-pass MMA, warp-local online softmax.
// BM=128 (8 warps x 16 rows), BN=64, DH=128, 256 threads, 1 CTA/SM.
// K AND V double-buffered; ONE __syncthreads per iteration (warp skew).
// P stays in REGISTERS: S-accumulator fragments repacked directly into PV
// A-fragments (C-frag layout == A-frag layout for m16n8k16).
// Q pre-scaled by SCALE at projection time.
// ===========================================================================
#define FBM 128
#define FBN 64
#define F_QH   0u          // 128x256B = 32768
#define F_QL   32768u
#define F_K0   65536u      // per buffer: hi 16384 | lo 16384; stride 32768
#define F_KLO  16384u
#define F_KSTR 32768u
#define F_V0   131072u     // per buffer: hi 16384 | lo 16384; stride 32768
#define F_VLO  16384u
#define F_VSTR 32768u
#define FLASH_SMEM 196608  // 192 KB

__device__ __forceinline__ void flash_load_q(uint32_t sb,
        const __nv_bfloat16* __restrict__ qh, const __nv_bfloat16* __restrict__ ql) {
    const int tid = threadIdx.x;
#pragma unroll
    for (int l = 0; l < 8; l++) {
        int e = tid + l * 256;
        int r = e >> 4, c = e & 15;
        int cp_ = c ^ (r & 7);
        uint32_t doff = (uint32_t)(r * 256 + cp_ * 16);
        cp16(sb + F_QH + doff, qh + r * 128 + c * 8);
        cp16(sb + F_QL + doff, ql + r * 128 + c * 8);
    }
}
__device__ __forceinline__ void flash_load_k(uint32_t dst,
        const __nv_bfloat16* __restrict__ kh, const __nv_bfloat16* __restrict__ kl) {
    const int tid = threadIdx.x;
#pragma unroll
    for (int l = 0; l < 4; l++) {
        int e = tid + l * 256;
        int r = e >> 4, c = e & 15;
        int cp_ = c ^ (r & 7);
        uint32_t doff = (uint32_t)(r * 256 + cp_ * 16);
        cp16(dst + doff, kh + r * 128 + c * 8);
        cp16(dst + F_KLO + doff, kl + r * 128 + c * 8);
    }
}
__device__ __forceinline__ void flash_load_v(uint32_t dst,
        const __nv_bfloat16* __restrict__ vh, const __nv_bfloat16* __restrict__ vl) {
    const int tid = threadIdx.x;
#pragma unroll
    for (int l = 0; l < 4; l++) {
        int e = tid + l * 256;
        int r = e >> 3, c = e & 7;
        int cp_ = c ^ (r & 7);
        uint32_t doff = (uint32_t)(r * 128 + cp_ * 16);
        cp16(dst + doff, vh + (size_t)r * Tt + c * 8);
        cp16(dst + F_VLO + doff, vl + (size_t)r * Tt + c * 8);
    }
}

__global__ __launch_bounds__(256, 1)
void flash_tc()
{
    extern __shared__ char smc[];
    const uint32_t sb = smem_u32(smc);
    const int qb = (gridDim.x - 1) - blockIdx.x;    // longest-job-first
    const int h  = blockIdx.y;
    const int b  = blockIdx.z;
    const int q0 = qb * FBM;
    const int tid  = threadIdx.x;
    const int w    = tid >> 5;
    const int lane = tid & 31;
    const int q4   = lane & 3;
    const int rl   = lane >> 2;
    const int lr   = lane & 7;
    const int g    = lane >> 3;

    // ldmatrix row-base addresses (chunk xor applied per-ks at use site)
    const uint32_t qRow = sb + F_QH + (uint32_t)((w * 16 + (g & 1) * 8 + lr) * 256);
    const uint32_t kRowOff = (uint32_t)(((g >> 1) * 8 + lr) * 256);   // + jj*4096, rel to kbuf
    const uint32_t vRowOff = (uint32_t)(((g >> 1) * 8 + lr) * 128);   // + ntp*2048, rel to vbuf
    const int aKH = g >> 1;    // A-side chunk half (Q)
    const int bKH = g & 1;     // B-side chunk half (K, V)

    const size_t bh = (size_t)(b * Hh + h) * Tt;
    const __nv_bfloat16* kbh = g_kh + bh * DHd;
    const __nv_bfloat16* kbl = g_kl + bh * DHd;
    const __nv_bfloat16* vbh = g_vth + (size_t)(b * Hh + h) * DHd * Tt;
    const __nv_bfloat16* vbl = g_vtl + (size_t)(b * Hh + h) * DHd * Tt;

    flash_load_q(sb, g_qh + (bh + q0) * DHd, g_ql + (bh + q0) * DHd);
    flash_load_k(sb + F_K0, kbh, kbl);
    flash_load_v(sb + F_V0, vbh, vbl);
    CP_COMMIT();

    float m_lo = -1e30f, m_hi = -1e30f, l_lo = 0.f, l_hi = 0.f;
    float o[16][4];
#pragma unroll
    for (int nt = 0; nt < 16; nt++)
#pragma unroll
        for (int r = 0; r < 4; r++) o[nt][r] = 0.f;

    const int rowbase = q0 + w * 16;
    const int nkt = 2 * qb + 2;

    for (int t = 0; t < nkt; t++) {
        const int k0 = t * FBN;
        const bool active = (k0 <= rowbase + 15);
        CP_WAIT0();            // K_t and V_t arrived
        __syncthreads();       // SINGLE barrier: protects buffer (t+1)&1 (read at t-1)

        if (t + 1 < nkt) {
            flash_load_k(sb + F_K0 + (uint32_t)((t + 1) & 1) * F_KSTR,
                         kbh + (size_t)(t + 1) * FBN * DHd,
                         kbl + (size_t)(t + 1) * FBN * DHd);
            flash_load_v(sb + F_V0 + (uint32_t)((t + 1) & 1) * F_VSTR,
                         vbh + (size_t)(t + 1) * FBN, vbl + (size_t)(t + 1) * FBN);
            CP_COMMIT();
        }

        if (active) {
            const uint32_t kbuf = sb + F_K0 + (uint32_t)(t & 1) * F_KSTR;
            float sacc[8][4];
#pragma unroll
            for (int j = 0; j < 8; j++)
#pragma unroll
                for (int r = 0; r < 4; r++) sacc[j][r] = 0.f;

#pragma unroll
            for (int ks = 0; ks < 8; ks++) {
                const uint32_t ca = (uint32_t)(((ks * 2 + aKH) ^ lr) * 16);
                const uint32_t cb = (uint32_t)(((ks * 2 + bKH) ^ lr) * 16);
                uint32_t ah[4], al[4];
                ldsm_x4(ah, qRow + ca);
                ldsm_x4(al, qRow + (F_QL - F_QH) + ca);
#pragma unroll
                for (int jj = 0; jj < 4; jj++) {
                    uint32_t bh4[4], bl4[4];
                    ldsm_x4(bh4, kbuf + kRowOff + (uint32_t)(jj * 4096) + cb);
                    ldsm_x4(bl4, kbuf + F_KLO + kRowOff + (uint32_t)(jj * 4096) + cb);
                    mma_bf16(sacc[2 * jj], ah, bh4[0], bh4[1]);
                    mma_bf16(sacc[2 * jj], al, bh4[0], bh4[1]);
                    mma_bf16(sacc[2 * jj], ah, bl4[0], bl4[1]);
                    mma_bf16(sacc[2 * jj + 1], ah, bh4[2], bh4[3]);
                    mma_bf16(sacc[2 * jj + 1], al, bh4[2], bh4[3]);
                    mma_bf16(sacc[2 * jj + 1], ah, bl4[2], bl4[3]);
                }
            }

            // Causal mask + warp-local online softmax (q pre-scaled)
            const int R_lo = rowbase + rl;
            const int R_hi = R_lo + 8;
            const bool needmask = (k0 + FBN - 1) > rowbase;
            float tl = -1e30f, th = -1e30f;
#pragma unroll
            for (int j = 0; j < 8; j++) {
                if (needmask) {
                    const int C = k0 + j * 8 + 2 * q4;
                    if (C > R_lo)     sacc[j][0] = -1e30f;
                    if (C + 1 > R_lo) sacc[j][1] = -1e30f;
                    if (C > R_hi)     sacc[j][2] = -1e30f;
                    if (C + 1 > R_hi) sacc[j][3] = -1e30f;
                }
                tl = fmaxf(tl, fmaxf(sacc[j][0], sacc[j][1]));
                th = fmaxf(th, fmaxf(sacc[j][2], sacc[j][3]));
            }
            tl = fmaxf(tl, __shfl_xor_sync(0xffffffffu, tl, 1));
            tl = fmaxf(tl, __shfl_xor_sync(0xffffffffu, tl, 2));
            th = fmaxf(th, __shfl_xor_sync(0xffffffffu, th, 1));
            th = fmaxf(th, __shfl_xor_sync(0xffffffffu, th, 2));

            const float mn_lo = fmaxf(m_lo, tl);
            const float mn_hi = fmaxf(m_hi, th);
            const float a_lo = __expf(m_lo - mn_lo);
            const float a_hi = __expf(m_hi - mn_hi);
            m_lo = mn_lo; m_hi = mn_hi;

            // exp + pack P straight into PV A-fragments (C-frag == A-frag layout)
            float sum_lo = 0.f, sum_hi = 0.f;
            uint32_t phA[4][4], plA[4][4];
#pragma unroll
            for (int j = 0; j < 8; j++) {
                float p0 = __expf(sacc[j][0] - mn_lo);
                float p1 = __expf(sacc[j][1] - mn_lo);
                float p2 = __expf(sacc[j][2] - mn_hi);
                float p3 = __expf(sacc[j][3] - mn_hi);
                sum_lo += p0 + p1;
                sum_hi += p2 + p3;
                const int ks = j >> 1;
                const int sl = (j & 1) * 2;
                uint32_t hh, ll;
                bf16_split2(p0, p1, hh, ll);
                phA[ks][sl]     = hh;
                plA[ks][sl]     = ll;
                bf16_split2(p2, p3, hh, ll);
                phA[ks][sl + 1] = hh;
                plA[ks][sl + 1] = ll;
            }
            sum_lo += __shfl_xor_sync(0xffffffffu, sum_lo, 1);
            sum_lo += __shfl_xor_sync(0xffffffffu, sum_lo, 2);
            sum_hi += __shfl_xor_sync(0xffffffffu, sum_hi, 1);
            sum_hi += __shfl_xor_sync(0xffffffffu, sum_hi, 2);
            l_lo = l_lo * a_lo + sum_lo;
            l_hi = l_hi * a_hi + sum_hi;

#pragma unroll
            for (int nt = 0; nt < 16; nt++) {
                o[nt][0] *= a_lo; o[nt][1] *= a_lo;
                o[nt][2] *= a_hi; o[nt][3] *= a_hi;
            }

            // O += P @ V  (3-pass bf16, P from registers)
            const uint32_t vbuf = sb + F_V0 + (uint32_t)(t & 1) * F_VSTR;
#pragma unroll
            for (int ks = 0; ks < 4; ks++) {
                const uint32_t cb = (uint32_t)(((ks * 2 + bKH) ^ lr) * 16);
#pragma unroll
                for (int ntp = 0; ntp < 8; ntp++) {
                    uint32_t vh4[4], vl4[4];
                    ldsm_x4(vh4, vbuf + vRowOff + (uint32_t)(ntp * 2048) + cb);
                    ldsm_x4(vl4, vbuf + F_VLO + vRowOff + (uint32_t)(ntp * 2048) + cb);
                    mma_bf16(o[2 * ntp], phA[ks], vh4[0], vh4[1]);
                    mma_bf16(o[2 * ntp], plA[ks], vh4[0], vh4[1]);
                    mma_bf16(o[2 * ntp], phA[ks], vl4[0], vl4[1]);
                    mma_bf16(o[2 * ntp + 1], phA[ks], vh4[2], vh4[3]);
                    mma_bf16(o[2 * ntp + 1], plA[ks], vh4[2], vh4[3]);
                    mma_bf16(o[2 * ntp + 1], phA[ks], vl4[2], vl4[3]);
                }
            }
        }
    }

    // Epilogue: divide by l, split, write att hi/lo [B,T,D]
    const float il_lo = 1.f / l_lo;
    const float il_hi = 1.f / l_hi;
    __nv_bfloat16* oh = g_atth + ((size_t)(b * Tt + rowbase)) * Dd + h * DHd;
    __nv_bfloat16* ol = g_attl + ((size_t)(b * Tt + rowbase)) * Dd + h * DHd;
#pragma unroll
    for (int nt = 0; nt < 16; nt++) {
        uint32_t hh, ll;
        size_t idx0 = (size_t)rl * Dd + nt * 8 + 2 * q4;
        bf16_split2(o[nt][0] * il_lo, o[nt][1] * il_lo, hh, ll);
        *(uint32_t*)(oh + idx0) = hh;
        *(uint32_t*)(ol + idx0) = ll;
        size_t idx1 = (size_t)(rl + 8) * Dd + nt * 8 + 2 * q4;
        bf16_split2(o[nt][2] * il_hi, o[nt][3] * il_hi, hh, ll);
        *(uint32_t*)(oh + idx1) = hh;
        *(uint32_t*)(ol + idx1) = ll;
    }
}

// ===========================================================================
extern "C" void kernel_launch(void* const* d_in, const int* in_sizes, int n_in,
                              void* d_out, int out_size)
{
    const float* x  = (const float*)d_in[0];
    const float* Wq = (const float*)d_in[1];
    const float* bq = (const float*)d_in[2];
    const float* Wk = (const float*)d_in[3];
    const float* bk = (const float*)d_in[4];
    const float* Wv = (const float*)d_in[5];
    const float* bv = (const float*)d_in[6];
    const float* Wo = (const float*)d_in[7];
    const float* bo = (const float*)d_in[8];
    float* out = (float*)d_out;

    __nv_bfloat16 *xh, *xl, *wth, *wtl, *atth, *attl;
    cudaGetSymbolAddress((void**)&xh,   g_xh);
    cudaGetSymbolAddress((void**)&xl,   g_xl);
    cudaGetSymbolAddress((void**)&wth,  g_wth);
    cudaGetSymbolAddress((void**)&wtl,  g_wtl);
    cudaGetSymbolAddress((void**)&atth, g_atth);
    cudaGetSymbolAddress((void**)&attl, g_attl);

    // 1) Convert inputs to bf16 hi/lo (x natural, all 4 W transposed, fused)
    conv_x_kernel<<<(Mm * Dd) / 1024, 256>>>(x, xh, xl);
    dim3 wgrid(Dd / 32, Dd / 32, 4);
    conv_w_all<<<wgrid, dim3(32, 8)>>>(Wq, Wk, Wv, Wo, wth, wtl);

    cudaFuncSetAttribute(gemm_qkv, cudaFuncAttributeMaxDynamicSharedMemorySize, GEMM_SMEM);
    cudaFuncSetAttribute(gemm_out, cudaFuncAttributeMaxDynamicSharedMemorySize, GEMM_SMEM);

    // 2) Fused QKV projections (one launch, one tail; q pre-scaled)
    dim3 qkvgrid(Dd / GBN, Mm / GBM, 3);   // (16, 64, 3)
    gemm_qkv<<<qkvgrid, 256, GEMM_SMEM>>>(xh, xl, wth, wtl, bq, bk, bv);

    // 3) Flash attention
    cudaFuncSetAttribute(flash_tc, cudaFuncAttributeMaxDynamicSharedMemorySize, FLASH_SMEM);
    dim3 fgrid(Tt / FBM, Hh, Bq);          // (16, 16, 4)
    flash_tc<<<fgrid, 256, FLASH_SMEM>>>();

    // 4) Output projection (fp32 out)
    dim3 ogrid(Dd / GBN, Mm / GBM);        // (16, 64)
    gemm_out<<<ogrid, 256, GEMM_SMEM>>>(atth, attl, wth + 3 * (size_t)Dd * Dd,
                                        wtl + 3 * (size_t)Dd * Dd, bo, out);
}